// round 9
// baseline (speedup 1.0000x reference)
#include <cuda_runtime.h>
#include <stdint.h>

#define NN_MAX 50000
#define E_MAX  800000
#define D_IN 128
#define D_RNI 32
#define D_H0 160
#define H 256

// ---------------- scratch (static device globals; no allocs allowed) --------
__device__ __align__(16) float g_xt [NN_MAX * H];
__device__ __align__(16) float g_agg[NN_MAX * H];
__device__ __align__(16) float g_dis[NN_MAX];
__device__ __align__(16) int   g_deg[NN_MAX];
__device__ __align__(16) int   g_rowstart[NN_MAX];
__device__ __align__(16) int   g_cursor[NN_MAX];
__device__ __align__(16) int   g_csr_src[E_MAX];
__device__ int g_is64;

// ---------------- edge-index dtype detection ---------------------------------
__global__ void detect_kernel(const void* __restrict__ ei, int n) {
    if (threadIdx.x == 0 && blockIdx.x == 0) {
        const long long* p = (const long long*)ei;
        int ok = 1;
        for (int i = 0; i < 512; i++) {
            long long v = p[i];
            if (v < 0 || v >= (long long)n) { ok = 0; break; }
        }
        g_is64 = ok;
    }
}

__device__ __forceinline__ int load_idx(const void* ei, long long i, int is64) {
    return is64 ? (int)((const long long*)ei)[i] : ((const int*)ei)[i];
}

__global__ void count_deg_kernel(const void* __restrict__ ei, int* __restrict__ deg,
                                 int e, int n) {
    int idx = blockIdx.x * blockDim.x + threadIdx.x;
    if (idx >= e) return;
    int is64 = g_is64;
    int d = load_idx(ei, (long long)e + idx, is64);
    if (d >= 0 && d < n) atomicAdd(&deg[d], 1);
}

// warp-shuffle exclusive scan of deg -> row_start + cursor; also dis = rsqrt(deg+1)
__global__ void scan_dis_kernel(const int* __restrict__ deg, int* __restrict__ row_start,
                                int* __restrict__ cursor, float* __restrict__ dis, int n) {
    __shared__ int warpsum[32];
    int tid = threadIdx.x;
    int lane = tid & 31;
    int wid = tid >> 5;
    int carry = 0;
    for (int base = 0; base < n; base += 1024) {
        int i = base + tid;
        int v = (i < n) ? deg[i] : 0;
        int s = v;
#pragma unroll
        for (int off = 1; off < 32; off <<= 1) {
            int t = __shfl_up_sync(0xffffffff, s, off);
            if (lane >= off) s += t;
        }
        if (lane == 31) warpsum[wid] = s;
        __syncthreads();
        if (wid == 0) {
            int w = warpsum[lane];
#pragma unroll
            for (int off = 1; off < 32; off <<= 1) {
                int t = __shfl_up_sync(0xffffffff, w, off);
                if (lane >= off) w += t;
            }
            warpsum[lane] = w;
        }
        __syncthreads();
        int warp_excl = (wid == 0) ? 0 : warpsum[wid - 1];
        int total = warpsum[31];
        if (i < n) {
            int ex = carry + warp_excl + s - v;
            row_start[i] = ex;
            cursor[i] = ex;
            dis[i] = rsqrtf((float)v + 1.0f);
        }
        carry += total;
        __syncthreads();
    }
}

__global__ void csr_fill_kernel(const void* __restrict__ ei,
                                int* __restrict__ cursor, int* __restrict__ csr_src,
                                int e, int n) {
    int idx = blockIdx.x * blockDim.x + threadIdx.x;
    if (idx >= e) return;
    int is64 = g_is64;
    int d = load_idx(ei, (long long)e + idx, is64);
    int s = load_idx(ei, idx, is64);
    if (d < 0 || d >= n || s < 0 || s >= n) return;
    int p = atomicAdd(&cursor[d], 1);
    if (p >= 0 && p < E_MAX) csr_src[p] = s;
}

// gather-aggregate: 64 threads per node (float4 columns), 4 nodes per block.
__global__ void gather_kernel(const float* __restrict__ xt, const float* __restrict__ dis,
                              const int* __restrict__ row_start, const int* __restrict__ deg,
                              const int* __restrict__ csr_src, const float* __restrict__ bias,
                              float* __restrict__ agg, int n) {
    int node = blockIdx.x * 4 + (threadIdx.x >> 6);
    int c4 = threadIdx.x & 63;
    if (node >= n) return;
    int start = row_start[node];
    int d = deg[node];
    const float4* xt4 = reinterpret_cast<const float4*>(xt);

    float4 a0 = make_float4(0.f, 0.f, 0.f, 0.f);
    float4 a1 = make_float4(0.f, 0.f, 0.f, 0.f);
    int j = 0;
    for (; j + 2 <= d; j += 2) {
        int s0 = __ldg(&csr_src[start + j]);
        int s1 = __ldg(&csr_src[start + j + 1]);
        float w0 = __ldg(&dis[s0]);
        float w1 = __ldg(&dis[s1]);
        float4 v0 = __ldg(&xt4[(size_t)s0 * 64 + c4]);
        float4 v1 = __ldg(&xt4[(size_t)s1 * 64 + c4]);
        a0.x = fmaf(v0.x, w0, a0.x); a0.y = fmaf(v0.y, w0, a0.y);
        a0.z = fmaf(v0.z, w0, a0.z); a0.w = fmaf(v0.w, w0, a0.w);
        a1.x = fmaf(v1.x, w1, a1.x); a1.y = fmaf(v1.y, w1, a1.y);
        a1.z = fmaf(v1.z, w1, a1.z); a1.w = fmaf(v1.w, w1, a1.w);
    }
    if (j < d) {
        int s0 = __ldg(&csr_src[start + j]);
        float w0 = __ldg(&dis[s0]);
        float4 v0 = __ldg(&xt4[(size_t)s0 * 64 + c4]);
        a0.x = fmaf(v0.x, w0, a0.x); a0.y = fmaf(v0.y, w0, a0.y);
        a0.z = fmaf(v0.z, w0, a0.z); a0.w = fmaf(v0.w, w0, a0.w);
    }
    a0.x += a1.x; a0.y += a1.y; a0.z += a1.z; a0.w += a1.w;

    float dd = dis[node];
    float4 self = xt4[(size_t)node * 64 + c4];
    float4 b = reinterpret_cast<const float4*>(bias)[c4];
    float4 r;
    r.x = fmaf(dd, fmaf(self.x, dd, a0.x), b.x);
    r.y = fmaf(dd, fmaf(self.y, dd, a0.y), b.y);
    r.z = fmaf(dd, fmaf(self.z, dd, a0.z), b.z);
    r.w = fmaf(dd, fmaf(self.w, dd, a0.w), b.w);
    reinterpret_cast<float4*>(agg)[(size_t)node * 64 + c4] = r;
}

// ---------------- bf16x3 tensor-core GEMM (m16n8k16) + ldmatrix ---------------
__device__ __forceinline__ uint32_t pack_bf(float lo, float hi) {
    uint32_t r;
    asm("cvt.rn.bf16x2.f32 %0, %1, %2;" : "=r"(r) : "f"(hi), "f"(lo));
    return r;
}

__device__ __forceinline__ void split_pair(float a0, float a1, uint32_t& h, uint32_t& l) {
    h = pack_bf(a0, a1);
    float h0 = __uint_as_float(h << 16);
    float h1 = __uint_as_float(h & 0xFFFF0000u);
    l = pack_bf(a0 - h0, a1 - h1);
}

__device__ __forceinline__ void mma_bf16(float (&d)[4], const uint32_t (&a)[4],
                                         const uint32_t (&b)[2]) {
    asm("mma.sync.aligned.m16n8k16.row.col.f32.bf16.bf16.f32 "
        "{%0,%1,%2,%3}, {%4,%5,%6,%7}, {%8,%9}, {%0,%1,%2,%3};"
        : "+f"(d[0]), "+f"(d[1]), "+f"(d[2]), "+f"(d[3])
        : "r"(a[0]), "r"(a[1]), "r"(a[2]), "r"(a[3]), "r"(b[0]), "r"(b[1]));
}

__device__ __forceinline__ void ldsm_x4(uint32_t (&r)[4], uint32_t addr) {
    asm volatile("ldmatrix.sync.aligned.m8n8.x4.shared.b16 {%0,%1,%2,%3}, [%4];"
                 : "=r"(r[0]), "=r"(r[1]), "=r"(r[2]), "=r"(r[3]) : "r"(addr));
}

// TSTRIDE must be a multiple of 4 words: ldmatrix needs 16B-aligned row addresses.
// 20 words = 80B; 8-row LDSM bases mod 32 banks = {0,20,8,28,16,4,24,12} -> conflict-free.
#define TSTRIDE 20
#define TILE_WORDS (128 * TSTRIDE)
#define STAGE_WORDS (4 * TILE_WORDS)
#define GEMM_SMEM_BYTES (2 * STAGE_WORDS * 4)   // 81920

template<bool SPLIT_A, bool RELU_IN, bool ADD_BIAS>
__global__ void __launch_bounds__(256, 2)
mma_gemm(const float* __restrict__ A, const float* __restrict__ A2,
         const float* __restrict__ B,
         const float* __restrict__ bias, float* __restrict__ C,
         int M, int N, int K) {
    extern __shared__ uint32_t sm[];
    const uint32_t sm_u32 = (uint32_t)__cvta_generic_to_shared(sm);

    const int tid  = threadIdx.x;
    const int lane = tid & 31;
    const int warp = tid >> 5;
    const int wm = warp & 3;
    const int wn = warp >> 2;
    const int g = lane >> 2;
    const int t = lane & 3;
    const int bm = blockIdx.y * 128;
    const int bn = blockIdx.x * 128;

    // ldmatrix per-lane address offsets (in words)
    const int a_row = (lane & 7) + ((lane >> 3) & 1) * 8;
    const int a_kp  = ((lane >> 4) & 1) * 4;
    const int b_row = (lane & 7) + ((lane >> 4) & 1) * 8;
    const int b_kp  = ((lane >> 3) & 1) * 4;

    float acc[2][8][4];
#pragma unroll
    for (int mi = 0; mi < 2; mi++)
#pragma unroll
        for (int ni = 0; ni < 8; ni++)
#pragma unroll
            for (int r = 0; r < 4; r++) acc[mi][ni][r] = 0.0f;

    float4 pa[4];
    float4 pb[4];

    auto load_tiles = [&](int k0) {
#pragma unroll
        for (int i = 0; i < 4; i++) {
            int idx = i * 256 + tid;
            int m  = idx >> 3;
            int col = k0 + ((idx & 7) << 2);
            int gm = bm + m;
            if (gm < M) {
                if (SPLIT_A) {
                    pa[i] = (col < D_IN)
                        ? *reinterpret_cast<const float4*>(A  + (size_t)gm * D_IN  + col)
                        : *reinterpret_cast<const float4*>(A2 + (size_t)gm * D_RNI + (col - D_IN));
                } else {
                    pa[i] = *reinterpret_cast<const float4*>(A + (size_t)gm * K + col);
                }
            } else {
                pa[i] = make_float4(0.f, 0.f, 0.f, 0.f);
            }
        }
#pragma unroll
        for (int i = 0; i < 4; i++) {
            int idx = i * 256 + tid;
            int kp = idx >> 6;
            int np = idx & 63;
            int krow = k0 + 2 * kp;
            const float* p0 = B + (size_t)krow * N + bn + 2 * np;
            float2 v0 = *reinterpret_cast<const float2*>(p0);
            float2 v1 = *reinterpret_cast<const float2*>(p0 + N);
            pb[i] = make_float4(v0.x, v0.y, v1.x, v1.y);
        }
    };

    auto store_tiles = [&](int s) {
        uint32_t* As_hi = sm + s * STAGE_WORDS;
        uint32_t* As_lo = As_hi + TILE_WORDS;
        uint32_t* Bs_hi = As_hi + 2 * TILE_WORDS;
        uint32_t* Bs_lo = As_hi + 3 * TILE_WORDS;
#pragma unroll
        for (int i = 0; i < 4; i++) {
            int idx = i * 256 + tid;
            int m  = idx >> 3;
            int kp = (idx & 7) << 1;
            float4 v = pa[i];
            if (RELU_IN) {
                v.x = fmaxf(v.x, 0.f); v.y = fmaxf(v.y, 0.f);
                v.z = fmaxf(v.z, 0.f); v.w = fmaxf(v.w, 0.f);
            }
            uint32_t h0, l0, h1, l1;
            split_pair(v.x, v.y, h0, l0);
            split_pair(v.z, v.w, h1, l1);
            int base = m * TSTRIDE + kp;
            *reinterpret_cast<uint2*>(&As_hi[base]) = make_uint2(h0, h1);
            *reinterpret_cast<uint2*>(&As_lo[base]) = make_uint2(l0, l1);
        }
#pragma unroll
        for (int i = 0; i < 4; i++) {
            int idx = i * 256 + tid;
            int kp = idx >> 6;
            int np = idx & 63;
            float4 v = pb[i];
            uint32_t h0, l0, h1, l1;
            split_pair(v.x, v.z, h0, l0);
            split_pair(v.y, v.w, h1, l1);
            int b0 = (2 * np) * TSTRIDE + kp;
            int b1 = b0 + TSTRIDE;
            Bs_hi[b0] = h0; Bs_hi[b1] = h1;
            Bs_lo[b0] = l0; Bs_lo[b1] = l1;
        }
    };

    auto compute = [&](int s) {
        uint32_t As_hi_a = sm_u32 + (s * STAGE_WORDS) * 4;
        uint32_t As_lo_a = As_hi_a + TILE_WORDS * 4;
        uint32_t Bs_hi_a = As_hi_a + 2 * TILE_WORDS * 4;
        uint32_t Bs_lo_a = As_hi_a + 3 * TILE_WORDS * 4;
#pragma unroll
        for (int kk = 0; kk < 2; kk++) {
            int kpb = kk * 8;
            uint32_t ah[2][4], al[2][4];
#pragma unroll
            for (int mi = 0; mi < 2; mi++) {
                uint32_t off = ((wm * 32 + mi * 16 + a_row) * TSTRIDE + kpb + a_kp) * 4;
                ldsm_x4(ah[mi], As_hi_a + off);
                ldsm_x4(al[mi], As_lo_a + off);
            }
#pragma unroll
            for (int nip = 0; nip < 4; nip++) {
                uint32_t off = ((wn * 64 + nip * 16 + b_row) * TSTRIDE + kpb + b_kp) * 4;
                uint32_t bh4[4], bl4[4];
                ldsm_x4(bh4, Bs_hi_a + off);
                ldsm_x4(bl4, Bs_lo_a + off);
#pragma unroll
                for (int half = 0; half < 2; half++) {
                    int ni = nip * 2 + half;
                    uint32_t bh[2] = { bh4[2 * half], bh4[2 * half + 1] };
                    uint32_t bl[2] = { bl4[2 * half], bl4[2 * half + 1] };
#pragma unroll
                    for (int mi = 0; mi < 2; mi++) {
                        mma_bf16(acc[mi][ni], ah[mi], bh);
                        mma_bf16(acc[mi][ni], ah[mi], bl);
                        mma_bf16(acc[mi][ni], al[mi], bh);
                    }
                }
            }
        }
    };

    load_tiles(0);
    store_tiles(0);
    __syncthreads();

    int cur = 0;
    for (int k0 = 0; k0 < K; k0 += 32) {
        bool has_next = (k0 + 32 < K);
        if (has_next) load_tiles(k0 + 32);
        compute(cur);
        if (has_next) store_tiles(cur ^ 1);
        __syncthreads();
        cur ^= 1;
    }

#pragma unroll
    for (int mi = 0; mi < 2; mi++) {
#pragma unroll
        for (int ni = 0; ni < 8; ni++) {
            int row = bm + wm * 32 + mi * 16 + g;
            int col = bn + wn * 64 + ni * 8 + t * 2;
            float bx = 0.f, by = 0.f;
            if (ADD_BIAS) {
                float2 bb = *reinterpret_cast<const float2*>(bias + col);
                bx = bb.x; by = bb.y;
            }
            if (row < M) {
                float2 v = make_float2(acc[mi][ni][0] + bx, acc[mi][ni][1] + by);
                *reinterpret_cast<float2*>(C + (size_t)row * N + col) = v;
            }
            int row2 = row + 8;
            if (row2 < M) {
                float2 v = make_float2(acc[mi][ni][2] + bx, acc[mi][ni][3] + by);
                *reinterpret_cast<float2*>(C + (size_t)row2 * N + col) = v;
            }
        }
    }
}

// ---------------- launch ------------------------------------------------------
extern "C" void kernel_launch(void* const* d_in, const int* in_sizes, int n_in,
                              void* d_out, int out_size) {
    const float* x     = (const float*)d_in[0];
    const float* rni   = (const float*)d_in[1];
    const void*  ei    = d_in[2];
    const float* W1    = (const float*)d_in[3];
    const float* b1    = (const float*)d_in[4];
    const float* W2    = (const float*)d_in[5];
    const float* b2    = (const float*)d_in[6];
    const float* Wout  = (const float*)d_in[7];
    const float* bout  = (const float*)d_in[8];
    float* out = (float*)d_out;

    int n = in_sizes[0] / D_IN;
    int e = in_sizes[2] / 2;

    float *xt, *agg, *dis;
    int *deg, *row_start, *cursor, *csr_src;
    cudaGetSymbolAddress((void**)&xt,        g_xt);
    cudaGetSymbolAddress((void**)&agg,       g_agg);
    cudaGetSymbolAddress((void**)&dis,       g_dis);
    cudaGetSymbolAddress((void**)&deg,       g_deg);
    cudaGetSymbolAddress((void**)&row_start, g_rowstart);
    cudaGetSymbolAddress((void**)&cursor,    g_cursor);
    cudaGetSymbolAddress((void**)&csr_src,   g_csr_src);

    cudaFuncSetAttribute(mma_gemm<true,  false, false>, cudaFuncAttributeMaxDynamicSharedMemorySize, GEMM_SMEM_BYTES);
    cudaFuncSetAttribute(mma_gemm<false, true,  false>, cudaFuncAttributeMaxDynamicSharedMemorySize, GEMM_SMEM_BYTES);
    cudaFuncSetAttribute(mma_gemm<false, true,  true >, cudaFuncAttributeMaxDynamicSharedMemorySize, GEMM_SMEM_BYTES);

    // prep (4th kernel launch = mma_gemm for the ncu capture window)
    detect_kernel<<<1, 32>>>(ei, n);
    cudaMemsetAsync(deg, 0, (size_t)n * sizeof(int));
    count_deg_kernel<<<(e + 255) / 256, 256>>>(ei, deg, e, n);
    scan_dis_kernel<<<1, 1024>>>(deg, row_start, cursor, dis, n);

    dim3 gemm_grid(H / 128, (n + 127) / 128);
    int gather_grid = (n + 3) / 4;

    // layer 1 GEMM; CSR fill overlaps (only the gather needs it)
    mma_gemm<true, false, false><<<gemm_grid, 256, GEMM_SMEM_BYTES>>>(x, rni, W1, nullptr, xt, n, H, D_H0);
    csr_fill_kernel<<<(e + 255) / 256, 256>>>(ei, cursor, csr_src, e, n);
    gather_kernel<<<gather_grid, 256>>>(xt, dis, row_start, deg, csr_src, b1, agg, n);

    // layer 2
    mma_gemm<false, true, false><<<gemm_grid, 256, GEMM_SMEM_BYTES>>>(agg, nullptr, W2, nullptr, xt, n, H, H);
    gather_kernel<<<gather_grid, 256>>>(xt, dis, row_start, deg, csr_src, b2, agg, n);

    // output
    mma_gemm<false, true, true><<<gemm_grid, 256, GEMM_SMEM_BYTES>>>(agg, nullptr, Wout, bout, out, n, H, H);
}

// round 11
// speedup vs baseline: 1.0519x; 1.0519x over previous
#include <cuda_runtime.h>
#include <stdint.h>

#define NN_MAX 50000
#define E_MAX  800000
#define D_IN 128
#define D_RNI 32
#define D_H0 160
#define H 256

// ---------------- scratch (static device globals; no allocs allowed) --------
__device__ __align__(16) float g_xt [NN_MAX * H];
__device__ __align__(16) float g_agg[NN_MAX * H];
__device__ __align__(16) float g_dis[NN_MAX];
__device__ __align__(16) int   g_deg[NN_MAX];
__device__ __align__(16) int   g_rowstart[NN_MAX];
__device__ __align__(16) int   g_cursor[NN_MAX];
__device__ __align__(16) int   g_csr_src[E_MAX];
__device__ int g_is64;

// ---------------- edge-index dtype detection ---------------------------------
__global__ void detect_kernel(const void* __restrict__ ei, int n) {
    if (threadIdx.x == 0 && blockIdx.x == 0) {
        const long long* p = (const long long*)ei;
        int ok = 1;
        for (int i = 0; i < 512; i++) {
            long long v = p[i];
            if (v < 0 || v >= (long long)n) { ok = 0; break; }
        }
        g_is64 = ok;
    }
}

__device__ __forceinline__ int load_idx(const void* ei, long long i, int is64) {
    return is64 ? (int)((const long long*)ei)[i] : ((const int*)ei)[i];
}

__global__ void count_deg_kernel(const void* __restrict__ ei, int* __restrict__ deg,
                                 int e, int n) {
    int idx = blockIdx.x * blockDim.x + threadIdx.x;
    if (idx >= e) return;
    int is64 = g_is64;
    int d = load_idx(ei, (long long)e + idx, is64);
    if (d >= 0 && d < n) atomicAdd(&deg[d], 1);
}

// warp-shuffle exclusive scan of deg -> row_start + cursor; also dis = rsqrt(deg+1)
__global__ void scan_dis_kernel(const int* __restrict__ deg, int* __restrict__ row_start,
                                int* __restrict__ cursor, float* __restrict__ dis, int n) {
    __shared__ int warpsum[32];
    int tid = threadIdx.x;
    int lane = tid & 31;
    int wid = tid >> 5;
    int carry = 0;
    for (int base = 0; base < n; base += 1024) {
        int i = base + tid;
        int v = (i < n) ? deg[i] : 0;
        int s = v;
#pragma unroll
        for (int off = 1; off < 32; off <<= 1) {
            int t = __shfl_up_sync(0xffffffff, s, off);
            if (lane >= off) s += t;
        }
        if (lane == 31) warpsum[wid] = s;
        __syncthreads();
        if (wid == 0) {
            int w = warpsum[lane];
#pragma unroll
            for (int off = 1; off < 32; off <<= 1) {
                int t = __shfl_up_sync(0xffffffff, w, off);
                if (lane >= off) w += t;
            }
            warpsum[lane] = w;
        }
        __syncthreads();
        int warp_excl = (wid == 0) ? 0 : warpsum[wid - 1];
        int total = warpsum[31];
        if (i < n) {
            int ex = carry + warp_excl + s - v;
            row_start[i] = ex;
            cursor[i] = ex;
            dis[i] = rsqrtf((float)v + 1.0f);
        }
        carry += total;
        __syncthreads();
    }
}

__global__ void csr_fill_kernel(const void* __restrict__ ei,
                                int* __restrict__ cursor, int* __restrict__ csr_src,
                                int e, int n) {
    int idx = blockIdx.x * blockDim.x + threadIdx.x;
    if (idx >= e) return;
    int is64 = g_is64;
    int d = load_idx(ei, (long long)e + idx, is64);
    int s = load_idx(ei, idx, is64);
    if (d < 0 || d >= n || s < 0 || s >= n) return;
    int p = atomicAdd(&cursor[d], 1);
    if (p >= 0 && p < E_MAX) csr_src[p] = s;
}

// gather-aggregate: 64 threads per node (float4 columns), 4 nodes per block.
__global__ void gather_kernel(const float* __restrict__ xt, const float* __restrict__ dis,
                              const int* __restrict__ row_start, const int* __restrict__ deg,
                              const int* __restrict__ csr_src, const float* __restrict__ bias,
                              float* __restrict__ agg, int n) {
    int node = blockIdx.x * 4 + (threadIdx.x >> 6);
    int c4 = threadIdx.x & 63;
    if (node >= n) return;
    int start = row_start[node];
    int d = deg[node];
    const float4* xt4 = reinterpret_cast<const float4*>(xt);

    float4 a0 = make_float4(0.f, 0.f, 0.f, 0.f);
    float4 a1 = make_float4(0.f, 0.f, 0.f, 0.f);
    int j = 0;
    for (; j + 2 <= d; j += 2) {
        int s0 = __ldg(&csr_src[start + j]);
        int s1 = __ldg(&csr_src[start + j + 1]);
        float w0 = __ldg(&dis[s0]);
        float w1 = __ldg(&dis[s1]);
        float4 v0 = __ldg(&xt4[(size_t)s0 * 64 + c4]);
        float4 v1 = __ldg(&xt4[(size_t)s1 * 64 + c4]);
        a0.x = fmaf(v0.x, w0, a0.x); a0.y = fmaf(v0.y, w0, a0.y);
        a0.z = fmaf(v0.z, w0, a0.z); a0.w = fmaf(v0.w, w0, a0.w);
        a1.x = fmaf(v1.x, w1, a1.x); a1.y = fmaf(v1.y, w1, a1.y);
        a1.z = fmaf(v1.z, w1, a1.z); a1.w = fmaf(v1.w, w1, a1.w);
    }
    if (j < d) {
        int s0 = __ldg(&csr_src[start + j]);
        float w0 = __ldg(&dis[s0]);
        float4 v0 = __ldg(&xt4[(size_t)s0 * 64 + c4]);
        a0.x = fmaf(v0.x, w0, a0.x); a0.y = fmaf(v0.y, w0, a0.y);
        a0.z = fmaf(v0.z, w0, a0.z); a0.w = fmaf(v0.w, w0, a0.w);
    }
    a0.x += a1.x; a0.y += a1.y; a0.z += a1.z; a0.w += a1.w;

    float dd = dis[node];
    float4 self = xt4[(size_t)node * 64 + c4];
    float4 b = reinterpret_cast<const float4*>(bias)[c4];
    float4 r;
    r.x = fmaf(dd, fmaf(self.x, dd, a0.x), b.x);
    r.y = fmaf(dd, fmaf(self.y, dd, a0.y), b.y);
    r.z = fmaf(dd, fmaf(self.z, dd, a0.z), b.z);
    r.w = fmaf(dd, fmaf(self.w, dd, a0.w), b.w);
    reinterpret_cast<float4*>(agg)[(size_t)node * 64 + c4] = r;
}

// ---------------- bf16x3 tensor-core GEMM (m16n8k16) --------------------------
// CTA 128x128, 128 threads = 4 warps (2m x 2n), warp tile 64x64 (Mi=4, Ni=8).
// BK=16. Smem rows = 8 words (one k16 of bf16x2 pairs), XOR swizzle
// phys_col = col ^ (4*((row>>2)&1)) -> fragment LDS hits all 32 banks.

__device__ __forceinline__ uint32_t pack_bf(float lo, float hi) {
    uint32_t r;
    asm("cvt.rn.bf16x2.f32 %0, %1, %2;" : "=r"(r) : "f"(hi), "f"(lo));
    return r;
}

__device__ __forceinline__ void split_pair(float a0, float a1, uint32_t& h, uint32_t& l) {
    h = pack_bf(a0, a1);
    float h0 = __uint_as_float(h << 16);
    float h1 = __uint_as_float(h & 0xFFFF0000u);
    l = pack_bf(a0 - h0, a1 - h1);
}

__device__ __forceinline__ void mma_bf16(float (&d)[4], const uint32_t (&a)[4],
                                         const uint32_t (&b)[2]) {
    asm("mma.sync.aligned.m16n8k16.row.col.f32.bf16.bf16.f32 "
        "{%0,%1,%2,%3}, {%4,%5,%6,%7}, {%8,%9}, {%0,%1,%2,%3};"
        : "+f"(d[0]), "+f"(d[1]), "+f"(d[2]), "+f"(d[3])
        : "r"(a[0]), "r"(a[1]), "r"(a[2]), "r"(a[3]), "r"(b[0]), "r"(b[1]));
}

#define TSW 8                     // words per smem row
#define TILE_W (128 * TSW)        // 1024 words per tile
#define STAGE_W (4 * TILE_W)      // A_hi, A_lo, B_hi, B_lo
#define GEMM_SMEM_BYTES (2 * STAGE_W * 4)   // 32768

template<bool SPLIT_A, bool RELU_IN, bool ADD_BIAS>
__global__ void __launch_bounds__(128, 2)
mma_gemm(const float* __restrict__ A, const float* __restrict__ A2,
         const float* __restrict__ B,
         const float* __restrict__ bias, float* __restrict__ C,
         int M, int K) {
    extern __shared__ uint32_t sm[];
    const int NW = H;  // 256

    const int tid  = threadIdx.x;
    const int lane = tid & 31;
    const int warp = tid >> 5;        // 0..3
    const int wm = warp & 1;
    const int wn = warp >> 1;
    const int g = lane >> 2;
    const int t = lane & 3;
    const int bm = blockIdx.y * 128;
    const int bn = blockIdx.x * 128;

    // swizzled fragment columns (row>>2 parity == g>>2 parity for 8-aligned bases)
    const int cs = (g & 4) ? 4 : 0;
    const int fc0 = t ^ cs;           // logical col t
    const int fc1 = (t + 4) ^ cs;     // logical col t+4

    float acc[4][8][4];
#pragma unroll
    for (int mi = 0; mi < 4; mi++)
#pragma unroll
        for (int ni = 0; ni < 8; ni++)
#pragma unroll
            for (int r = 0; r < 4; r++) acc[mi][ni][r] = 0.0f;

    float4 pa[4];   // A: 128m x 16k  = 512 float4, 4/thread
    float4 pb[4];   // B pairs: (kp 0..7) x (np 0..63) = 512 items, 4/thread

    auto load_tiles = [&](int k0) {
#pragma unroll
        for (int i = 0; i < 4; i++) {
            int idx = i * 128 + tid;
            int m  = idx >> 2;
            int col = k0 + ((idx & 3) << 2);
            int gm = bm + m;
            if (gm < M) {
                if (SPLIT_A) {
                    pa[i] = (col < D_IN)
                        ? *reinterpret_cast<const float4*>(A  + (size_t)gm * D_IN  + col)
                        : *reinterpret_cast<const float4*>(A2 + (size_t)gm * D_RNI + (col - D_IN));
                } else {
                    pa[i] = *reinterpret_cast<const float4*>(A + (size_t)gm * K + col);
                }
            } else {
                pa[i] = make_float4(0.f, 0.f, 0.f, 0.f);
            }
        }
#pragma unroll
        for (int i = 0; i < 4; i++) {
            int idx = i * 128 + tid;
            int kp = idx >> 6;            // 0..7
            int np = idx & 63;            // n-pair 0..63
            int krow = k0 + 2 * kp;
            const float* p0 = B + (size_t)krow * NW + bn + 2 * np;
            float2 v0 = *reinterpret_cast<const float2*>(p0);
            float2 v1 = *reinterpret_cast<const float2*>(p0 + NW);
            pb[i] = make_float4(v0.x, v0.y, v1.x, v1.y);
        }
    };

    auto store_tiles = [&](int s) {
        uint32_t* A_hi = sm + s * STAGE_W;
        uint32_t* A_lo = A_hi + TILE_W;
        uint32_t* B_hi = A_hi + 2 * TILE_W;
        uint32_t* B_lo = A_hi + 3 * TILE_W;
#pragma unroll
        for (int i = 0; i < 4; i++) {
            int idx = i * 128 + tid;
            int m  = idx >> 2;
            int kq = idx & 3;
            float4 v = pa[i];
            if (RELU_IN) {
                v.x = fmaxf(v.x, 0.f); v.y = fmaxf(v.y, 0.f);
                v.z = fmaxf(v.z, 0.f); v.w = fmaxf(v.w, 0.f);
            }
            uint32_t h0, l0, h1, l1;
            split_pair(v.x, v.y, h0, l0);
            split_pair(v.z, v.w, h1, l1);
            int sw = (m & 4) ? 4 : 0;
            int base = m * TSW + ((2 * kq) ^ sw);   // even -> uint2-aligned
            *reinterpret_cast<uint2*>(&A_hi[base]) = make_uint2(h0, h1);
            *reinterpret_cast<uint2*>(&A_lo[base]) = make_uint2(l0, l1);
        }
#pragma unroll
        for (int i = 0; i < 4; i++) {
            int idx = i * 128 + tid;
            int kp = idx >> 6;
            int np = idx & 63;
            float4 v = pb[i];
            uint32_t h0, l0, h1, l1;
            split_pair(v.x, v.z, h0, l0);   // n = 2np: (k even, k odd)
            split_pair(v.y, v.w, h1, l1);   // n = 2np+1
            int sw = (np & 2) ? 4 : 0;      // ((2np)>>2)&1
            int col = kp ^ sw;
            int r0 = (2 * np) * TSW + col;
            B_hi[r0] = h0; B_hi[r0 + TSW] = h1;
            B_lo[r0] = l0; B_lo[r0 + TSW] = l1;
        }
    };

    auto compute = [&](int s) {
        uint32_t* A_hi = sm + s * STAGE_W;
        uint32_t* A_lo = A_hi + TILE_W;
        uint32_t* B_hi = A_hi + 2 * TILE_W;
        uint32_t* B_lo = A_hi + 3 * TILE_W;
        uint32_t ah[4][4], al[4][4];
#pragma unroll
        for (int mi = 0; mi < 4; mi++) {
            int r0 = (wm * 64 + mi * 16 + g) * TSW;
            int r1 = r0 + 8 * TSW;
            ah[mi][0] = A_hi[r0 + fc0]; ah[mi][1] = A_hi[r1 + fc0];
            ah[mi][2] = A_hi[r0 + fc1]; ah[mi][3] = A_hi[r1 + fc1];
            al[mi][0] = A_lo[r0 + fc0]; al[mi][1] = A_lo[r1 + fc0];
            al[mi][2] = A_lo[r0 + fc1]; al[mi][3] = A_lo[r1 + fc1];
        }
#pragma unroll
        for (int ni = 0; ni < 8; ni++) {
            int nr = (wn * 64 + ni * 8 + g) * TSW;
            uint32_t bh[2] = { B_hi[nr + fc0], B_hi[nr + fc1] };
            uint32_t bl[2] = { B_lo[nr + fc0], B_lo[nr + fc1] };
#pragma unroll
            for (int mi = 0; mi < 4; mi++) {
                mma_bf16(acc[mi][ni], ah[mi], bh);
                mma_bf16(acc[mi][ni], ah[mi], bl);
                mma_bf16(acc[mi][ni], al[mi], bh);
            }
        }
    };

    load_tiles(0);
    store_tiles(0);
    __syncthreads();

    int cur = 0;
    for (int k0 = 0; k0 < K; k0 += 16) {
        bool has_next = (k0 + 16 < K);
        if (has_next) load_tiles(k0 + 16);
        compute(cur);
        if (has_next) store_tiles(cur ^ 1);
        __syncthreads();
        cur ^= 1;
    }

#pragma unroll
    for (int mi = 0; mi < 4; mi++) {
#pragma unroll
        for (int ni = 0; ni < 8; ni++) {
            int row = bm + wm * 64 + mi * 16 + g;
            int col = bn + wn * 64 + ni * 8 + t * 2;
            float bx = 0.f, by = 0.f;
            if (ADD_BIAS) {
                float2 bb = *reinterpret_cast<const float2*>(bias + col);
                bx = bb.x; by = bb.y;
            }
            if (row < M) {
                float2 v = make_float2(acc[mi][ni][0] + bx, acc[mi][ni][1] + by);
                *reinterpret_cast<float2*>(C + (size_t)row * NW + col) = v;
            }
            int row2 = row + 8;
            if (row2 < M) {
                float2 v = make_float2(acc[mi][ni][2] + bx, acc[mi][ni][3] + by);
                *reinterpret_cast<float2*>(C + (size_t)row2 * NW + col) = v;
            }
        }
    }
}

// ---------------- launch ------------------------------------------------------
extern "C" void kernel_launch(void* const* d_in, const int* in_sizes, int n_in,
                              void* d_out, int out_size) {
    const float* x     = (const float*)d_in[0];
    const float* rni   = (const float*)d_in[1];
    const void*  ei    = d_in[2];
    const float* W1    = (const float*)d_in[3];
    const float* b1    = (const float*)d_in[4];
    const float* W2    = (const float*)d_in[5];
    const float* b2    = (const float*)d_in[6];
    const float* Wout  = (const float*)d_in[7];
    const float* bout  = (const float*)d_in[8];
    float* out = (float*)d_out;

    int n = in_sizes[0] / D_IN;
    int e = in_sizes[2] / 2;

    float *xt, *agg, *dis;
    int *deg, *row_start, *cursor, *csr_src;
    cudaGetSymbolAddress((void**)&xt,        g_xt);
    cudaGetSymbolAddress((void**)&agg,       g_agg);
    cudaGetSymbolAddress((void**)&dis,       g_dis);
    cudaGetSymbolAddress((void**)&deg,       g_deg);
    cudaGetSymbolAddress((void**)&row_start, g_rowstart);
    cudaGetSymbolAddress((void**)&cursor,    g_cursor);
    cudaGetSymbolAddress((void**)&csr_src,   g_csr_src);

    // prep (4th kernel launch = mma_gemm for the ncu capture window)
    detect_kernel<<<1, 32>>>(ei, n);
    cudaMemsetAsync(deg, 0, (size_t)n * sizeof(int));
    count_deg_kernel<<<(e + 255) / 256, 256>>>(ei, deg, e, n);
    scan_dis_kernel<<<1, 1024>>>(deg, row_start, cursor, dis, n);

    dim3 gemm_grid(H / 128, (n + 127) / 128);
    int gather_grid = (n + 3) / 4;

    // layer 1 GEMM; CSR fill overlaps (only the gather needs it)
    mma_gemm<true, false, false><<<gemm_grid, 128, GEMM_SMEM_BYTES>>>(x, rni, W1, nullptr, xt, n, D_H0);
    csr_fill_kernel<<<(e + 255) / 256, 256>>>(ei, cursor, csr_src, e, n);
    gather_kernel<<<gather_grid, 256>>>(xt, dis, row_start, deg, csr_src, b1, agg, n);

    // layer 2
    mma_gemm<false, true, false><<<gemm_grid, 128, GEMM_SMEM_BYTES>>>(agg, nullptr, W2, nullptr, xt, n, H);
    gather_kernel<<<gather_grid, 256>>>(xt, dis, row_start, deg, csr_src, b2, agg, n);

    // output
    mma_gemm<false, true, true><<<gemm_grid, 128, GEMM_SMEM_BYTES>>>(agg, nullptr, Wout, bout, out, n, H);
}

// round 13
// speedup vs baseline: 1.0570x; 1.0049x over previous
#include <cuda_runtime.h>
#include <stdint.h>

#define NN_MAX 50000
#define E_MAX  800000
#define D_IN 128
#define D_RNI 32
#define D_H0 160
#define H 256
#define KP1 80      // k-pairs layer 1 (K=160)
#define KP2 128     // k-pairs layers 2/3 (K=256)

// ---------------- scratch (static device globals; no allocs allowed) --------
__device__ __align__(16) float    g_xt  [NN_MAX * H];
__device__ __align__(16) uint32_t g_ahi [NN_MAX * KP2];
__device__ __align__(16) uint32_t g_alo [NN_MAX * KP2];
__device__ __align__(16) uint32_t g_w1hi[H * KP1];
__device__ __align__(16) uint32_t g_w1lo[H * KP1];
__device__ __align__(16) uint32_t g_w2hi[H * KP2];
__device__ __align__(16) uint32_t g_w2lo[H * KP2];
__device__ __align__(16) uint32_t g_wohi[H * KP2];
__device__ __align__(16) uint32_t g_wolo[H * KP2];
__device__ __align__(16) float    g_dis[NN_MAX];
__device__ __align__(16) int      g_deg[NN_MAX];
__device__ __align__(16) int      g_rowstart[NN_MAX];
__device__ __align__(16) int      g_cursor[NN_MAX];
__device__ __align__(16) int      g_csr_src[E_MAX];
__device__ int g_is64;

// ---------------- bf16 split helpers -----------------------------------------
__device__ __forceinline__ uint32_t pack_bf(float lo, float hi) {
    uint32_t r;
    asm("cvt.rn.bf16x2.f32 %0, %1, %2;" : "=r"(r) : "f"(hi), "f"(lo));
    return r;
}
__device__ __forceinline__ void split_pair(float a0, float a1, uint32_t& h, uint32_t& l) {
    h = pack_bf(a0, a1);
    float h0 = __uint_as_float(h << 16);
    float h1 = __uint_as_float(h & 0xFFFF0000u);
    l = pack_bf(a0 - h0, a1 - h1);
}

// ---------------- edge-index dtype detection ---------------------------------
__global__ void detect_kernel(const void* __restrict__ ei, int n) {
    if (threadIdx.x == 0 && blockIdx.x == 0) {
        const long long* p = (const long long*)ei;
        int ok = 1;
        for (int i = 0; i < 512; i++) {
            long long v = p[i];
            if (v < 0 || v >= (long long)n) { ok = 0; break; }
        }
        g_is64 = ok;
    }
}

__device__ __forceinline__ int load_idx(const void* ei, long long i, int is64) {
    return is64 ? (int)((const long long*)ei)[i] : ((const int*)ei)[i];
}

__global__ void count_deg_kernel(const void* __restrict__ ei, int* __restrict__ deg,
                                 int e, int n) {
    int idx = blockIdx.x * blockDim.x + threadIdx.x;
    if (idx >= e) return;
    int is64 = g_is64;
    int d = load_idx(ei, (long long)e + idx, is64);
    if (d >= 0 && d < n) atomicAdd(&deg[d], 1);
}

__global__ void scan_dis_kernel(const int* __restrict__ deg, int* __restrict__ row_start,
                                int* __restrict__ cursor, float* __restrict__ dis, int n) {
    __shared__ int warpsum[32];
    int tid = threadIdx.x;
    int lane = tid & 31;
    int wid = tid >> 5;
    int carry = 0;
    for (int base = 0; base < n; base += 1024) {
        int i = base + tid;
        int v = (i < n) ? deg[i] : 0;
        int s = v;
#pragma unroll
        for (int off = 1; off < 32; off <<= 1) {
            int t = __shfl_up_sync(0xffffffff, s, off);
            if (lane >= off) s += t;
        }
        if (lane == 31) warpsum[wid] = s;
        __syncthreads();
        if (wid == 0) {
            int w = warpsum[lane];
#pragma unroll
            for (int off = 1; off < 32; off <<= 1) {
                int t = __shfl_up_sync(0xffffffff, w, off);
                if (lane >= off) w += t;
            }
            warpsum[lane] = w;
        }
        __syncthreads();
        int warp_excl = (wid == 0) ? 0 : warpsum[wid - 1];
        int total = warpsum[31];
        if (i < n) {
            int ex = carry + warp_excl + s - v;
            row_start[i] = ex;
            cursor[i] = ex;
            dis[i] = rsqrtf((float)v + 1.0f);
        }
        carry += total;
        __syncthreads();
    }
}

__global__ void csr_fill_kernel(const void* __restrict__ ei,
                                int* __restrict__ cursor, int* __restrict__ csr_src,
                                int e, int n) {
    int idx = blockIdx.x * blockDim.x + threadIdx.x;
    if (idx >= e) return;
    int is64 = g_is64;
    int d = load_idx(ei, (long long)e + idx, is64);
    int s = load_idx(ei, idx, is64);
    if (d < 0 || d >= n || s < 0 || s >= n) return;
    int p = atomicAdd(&cursor[d], 1);
    if (p >= 0 && p < E_MAX) csr_src[p] = s;
}

// convert [x|rni] -> pre-split bf16 hi/lo arrays, [node][KP1] uint32 each
__global__ void convert_x_kernel(const float* __restrict__ x, const float* __restrict__ rni,
                                 uint32_t* __restrict__ ahi, uint32_t* __restrict__ alo, int n) {
    int idx = blockIdx.x * blockDim.x + threadIdx.x;
    int total = n * KP1;
    if (idx >= total) return;
    int m = idx / KP1;
    int k = 2 * (idx - m * KP1);
    float v0, v1;
    if (k < D_IN) {
        v0 = x[(size_t)m * D_IN + k];
        v1 = x[(size_t)m * D_IN + k + 1];
    } else {
        v0 = rni[(size_t)m * D_RNI + (k - D_IN)];
        v1 = rni[(size_t)m * D_RNI + (k - D_IN) + 1];
    }
    uint32_t h, l;
    split_pair(v0, v1, h, l);
    ahi[idx] = h;
    alo[idx] = l;
}

// split + transpose weights: W[K][N] -> whi/wlo [N][KP]
__global__ void wsplit_kernel(const float* __restrict__ W,
                              uint32_t* __restrict__ whi, uint32_t* __restrict__ wlo, int kp_tot) {
    int idx = blockIdx.x * blockDim.x + threadIdx.x;
    if (idx >= H * kp_tot) return;
    int nn = idx / kp_tot;
    int kp = idx - nn * kp_tot;
    float v0 = W[(size_t)(2 * kp)     * H + nn];
    float v1 = W[(size_t)(2 * kp + 1) * H + nn];
    uint32_t h, l;
    split_pair(v0, v1, h, l);
    whi[idx] = h;
    wlo[idx] = l;
}

// gather-aggregate: 64 threads per node, 4 nodes per block.
// out = relu(dis[d]*(sum_s xt[s]*dis[s] + xt[d]*dis[d]) + bias), split into hi/lo
__global__ void gather_kernel(const float* __restrict__ xt, const float* __restrict__ dis,
                              const int* __restrict__ row_start, const int* __restrict__ deg,
                              const int* __restrict__ csr_src, const float* __restrict__ bias,
                              uint32_t* __restrict__ ohi, uint32_t* __restrict__ olo, int n) {
    int node = blockIdx.x * 4 + (threadIdx.x >> 6);
    int c4 = threadIdx.x & 63;
    if (node >= n) return;
    int start = row_start[node];
    int d = deg[node];
    const float4* xt4 = reinterpret_cast<const float4*>(xt);

    float4 a0 = make_float4(0.f, 0.f, 0.f, 0.f);
    float4 a1 = make_float4(0.f, 0.f, 0.f, 0.f);
    int j = 0;
    for (; j + 2 <= d; j += 2) {
        int s0 = __ldg(&csr_src[start + j]);
        int s1 = __ldg(&csr_src[start + j + 1]);
        float w0 = __ldg(&dis[s0]);
        float w1 = __ldg(&dis[s1]);
        float4 v0 = __ldg(&xt4[(size_t)s0 * 64 + c4]);
        float4 v1 = __ldg(&xt4[(size_t)s1 * 64 + c4]);
        a0.x = fmaf(v0.x, w0, a0.x); a0.y = fmaf(v0.y, w0, a0.y);
        a0.z = fmaf(v0.z, w0, a0.z); a0.w = fmaf(v0.w, w0, a0.w);
        a1.x = fmaf(v1.x, w1, a1.x); a1.y = fmaf(v1.y, w1, a1.y);
        a1.z = fmaf(v1.z, w1, a1.z); a1.w = fmaf(v1.w, w1, a1.w);
    }
    if (j < d) {
        int s0 = __ldg(&csr_src[start + j]);
        float w0 = __ldg(&dis[s0]);
        float4 v0 = __ldg(&xt4[(size_t)s0 * 64 + c4]);
        a0.x = fmaf(v0.x, w0, a0.x); a0.y = fmaf(v0.y, w0, a0.y);
        a0.z = fmaf(v0.z, w0, a0.z); a0.w = fmaf(v0.w, w0, a0.w);
    }
    a0.x += a1.x; a0.y += a1.y; a0.z += a1.z; a0.w += a1.w;

    float dd = dis[node];
    float4 self = xt4[(size_t)node * 64 + c4];
    float4 b = reinterpret_cast<const float4*>(bias)[c4];
    float4 r;
    r.x = fmaxf(fmaf(dd, fmaf(self.x, dd, a0.x), b.x), 0.f);
    r.y = fmaxf(fmaf(dd, fmaf(self.y, dd, a0.y), b.y), 0.f);
    r.z = fmaxf(fmaf(dd, fmaf(self.z, dd, a0.z), b.z), 0.f);
    r.w = fmaxf(fmaf(dd, fmaf(self.w, dd, a0.w), b.w), 0.f);

    uint32_t h0, l0, h1, l1;
    split_pair(r.x, r.y, h0, l0);
    split_pair(r.z, r.w, h1, l1);
    size_t base = (size_t)node * KP2 + 2 * c4;
    *reinterpret_cast<uint2*>(ohi + base) = make_uint2(h0, h1);
    *reinterpret_cast<uint2*>(olo + base) = make_uint2(l0, l1);
}

// ---------------- bf16x3 tensor-core GEMM (m16n8k16), pre-split inputs --------
// CTA 128x128, 256 threads = 8 warps (4m x 2n), warp tile 32x64. BK = 16 k-pairs.
// A: [m][kp] hi/lo uint32; W: [n][kp] hi/lo uint32 (pre-transposed). Smem stride
// 20 words -> conflict-free scalar fragment reads and aligned uint4 stores.

__device__ __forceinline__ void mma_bf16(float (&d)[4], const uint32_t (&a)[4],
                                         const uint32_t (&b)[2]) {
    asm("mma.sync.aligned.m16n8k16.row.col.f32.bf16.bf16.f32 "
        "{%0,%1,%2,%3}, {%4,%5,%6,%7}, {%8,%9}, {%0,%1,%2,%3};"
        : "+f"(d[0]), "+f"(d[1]), "+f"(d[2]), "+f"(d[3])
        : "r"(a[0]), "r"(a[1]), "r"(a[2]), "r"(a[3]), "r"(b[0]), "r"(b[1]));
}

#define TSTRIDE 20
#define TILE_W (128 * TSTRIDE)            // 2560 words
#define STAGE_W (4 * TILE_W)              // A_hi, A_lo, B_hi, B_lo
#define GEMM_SMEM_BYTES (2 * STAGE_W * 4) // 81920

template<bool ADD_BIAS>
__global__ void __launch_bounds__(256, 2)
mma_gemm(const uint32_t* __restrict__ Ahi, const uint32_t* __restrict__ Alo,
         const uint32_t* __restrict__ Whi, const uint32_t* __restrict__ Wlo,
         const float* __restrict__ bias, float* __restrict__ C,
         int M, int KPt) {
    extern __shared__ uint32_t sm[];
    const int NW = H;

    const int tid  = threadIdx.x;
    const int lane = tid & 31;
    const int warp = tid >> 5;
    const int wm = warp & 3;
    const int wn = warp >> 2;
    const int g = lane >> 2;
    const int t = lane & 3;
    const int bm = blockIdx.y * 128;
    const int bn = blockIdx.x * 128;

    float acc[2][8][4];
#pragma unroll
    for (int mi = 0; mi < 2; mi++)
#pragma unroll
        for (int ni = 0; ni < 8; ni++)
#pragma unroll
            for (int r = 0; r < 4; r++) acc[mi][ni][r] = 0.0f;

    uint4 pah[2], pal[2], pbh[2], pbl[2];

    auto load_tiles = [&](int kp0) {
#pragma unroll
        for (int i = 0; i < 2; i++) {
            int idx = i * 256 + tid;
            int m  = idx >> 2;
            int kp4 = (idx & 3) << 2;
            int gm = bm + m;
            if (gm < M) {
                size_t off = (size_t)gm * KPt + kp0 + kp4;
                pah[i] = *reinterpret_cast<const uint4*>(Ahi + off);
                pal[i] = *reinterpret_cast<const uint4*>(Alo + off);
            } else {
                pah[i] = make_uint4(0, 0, 0, 0);
                pal[i] = make_uint4(0, 0, 0, 0);
            }
        }
#pragma unroll
        for (int i = 0; i < 2; i++) {
            int idx = i * 256 + tid;
            int nn = idx >> 2;
            int kp4 = (idx & 3) << 2;
            size_t off = (size_t)(bn + nn) * KPt + kp0 + kp4;
            pbh[i] = *reinterpret_cast<const uint4*>(Whi + off);
            pbl[i] = *reinterpret_cast<const uint4*>(Wlo + off);
        }
    };

    auto store_tiles = [&](int s) {
        uint32_t* As_hi = sm + s * STAGE_W;
        uint32_t* As_lo = As_hi + TILE_W;
        uint32_t* Bs_hi = As_hi + 2 * TILE_W;
        uint32_t* Bs_lo = As_hi + 3 * TILE_W;
#pragma unroll
        for (int i = 0; i < 2; i++) {
            int idx = i * 256 + tid;
            int m  = idx >> 2;
            int kp4 = (idx & 3) << 2;
            int base = m * TSTRIDE + kp4;
            *reinterpret_cast<uint4*>(&As_hi[base]) = pah[i];
            *reinterpret_cast<uint4*>(&As_lo[base]) = pal[i];
        }
#pragma unroll
        for (int i = 0; i < 2; i++) {
            int idx = i * 256 + tid;
            int nn = idx >> 2;
            int kp4 = (idx & 3) << 2;
            int base = nn * TSTRIDE + kp4;
            *reinterpret_cast<uint4*>(&Bs_hi[base]) = pbh[i];
            *reinterpret_cast<uint4*>(&Bs_lo[base]) = pbl[i];
        }
    };

    auto compute = [&](int s) {
        uint32_t* As_hi = sm + s * STAGE_W;
        uint32_t* As_lo = As_hi + TILE_W;
        uint32_t* Bs_hi = As_hi + 2 * TILE_W;
        uint32_t* Bs_lo = As_hi + 3 * TILE_W;
#pragma unroll
        for (int kk = 0; kk < 2; kk++) {
            int kpb = kk * 8;
            uint32_t ah[2][4], al[2][4];
#pragma unroll
            for (int mi = 0; mi < 2; mi++) {
                int r0 = (wm * 32 + mi * 16 + g) * TSTRIDE;
                int r1 = r0 + 8 * TSTRIDE;
                int c0 = kpb + t;
                int c1 = c0 + 4;
                ah[mi][0] = As_hi[r0 + c0]; ah[mi][1] = As_hi[r1 + c0];
                ah[mi][2] = As_hi[r0 + c1]; ah[mi][3] = As_hi[r1 + c1];
                al[mi][0] = As_lo[r0 + c0]; al[mi][1] = As_lo[r1 + c0];
                al[mi][2] = As_lo[r0 + c1]; al[mi][3] = As_lo[r1 + c1];
            }
#pragma unroll
            for (int ni = 0; ni < 8; ni++) {
                int nr = (wn * 64 + ni * 8 + g) * TSTRIDE;
                uint32_t bh[2] = { Bs_hi[nr + kpb + t], Bs_hi[nr + kpb + t + 4] };
                uint32_t bl[2] = { Bs_lo[nr + kpb + t], Bs_lo[nr + kpb + t + 4] };
#pragma unroll
                for (int mi = 0; mi < 2; mi++) {
                    mma_bf16(acc[mi][ni], ah[mi], bh);
                    mma_bf16(acc[mi][ni], ah[mi], bl);
                    mma_bf16(acc[mi][ni], al[mi], bh);
                }
            }
        }
    };

    load_tiles(0);
    store_tiles(0);
    __syncthreads();

    int cur = 0;
    for (int kp0 = 0; kp0 < KPt; kp0 += 16) {
        bool has_next = (kp0 + 16 < KPt);
        if (has_next) load_tiles(kp0 + 16);
        compute(cur);
        if (has_next) store_tiles(cur ^ 1);
        __syncthreads();
        cur ^= 1;
    }

#pragma unroll
    for (int mi = 0; mi < 2; mi++) {
#pragma unroll
        for (int ni = 0; ni < 8; ni++) {
            int row = bm + wm * 32 + mi * 16 + g;
            int col = bn + wn * 64 + ni * 8 + t * 2;
            float bx = 0.f, by = 0.f;
            if (ADD_BIAS) {
                float2 bb = *reinterpret_cast<const float2*>(bias + col);
                bx = bb.x; by = bb.y;
            }
            if (row < M) {
                float2 v = make_float2(acc[mi][ni][0] + bx, acc[mi][ni][1] + by);
                *reinterpret_cast<float2*>(C + (size_t)row * NW + col) = v;
            }
            int row2 = row + 8;
            if (row2 < M) {
                float2 v = make_float2(acc[mi][ni][2] + bx, acc[mi][ni][3] + by);
                *reinterpret_cast<float2*>(C + (size_t)row2 * NW + col) = v;
            }
        }
    }
}

// ---------------- launch ------------------------------------------------------
extern "C" void kernel_launch(void* const* d_in, const int* in_sizes, int n_in,
                              void* d_out, int out_size) {
    const float* x     = (const float*)d_in[0];
    const float* rni   = (const float*)d_in[1];
    const void*  ei    = d_in[2];
    const float* W1    = (const float*)d_in[3];
    const float* b1    = (const float*)d_in[4];
    const float* W2    = (const float*)d_in[5];
    const float* b2    = (const float*)d_in[6];
    const float* Wout  = (const float*)d_in[7];
    const float* bout  = (const float*)d_in[8];
    float* out = (float*)d_out;

    int n = in_sizes[0] / D_IN;
    int e = in_sizes[2] / 2;

    float *xt, *dis;
    uint32_t *ahi, *alo, *w1hi, *w1lo, *w2hi, *w2lo, *wohi, *wolo;
    int *deg, *row_start, *cursor, *csr_src;
    cudaGetSymbolAddress((void**)&xt,        g_xt);
    cudaGetSymbolAddress((void**)&ahi,       g_ahi);
    cudaGetSymbolAddress((void**)&alo,       g_alo);
    cudaGetSymbolAddress((void**)&w1hi,      g_w1hi);
    cudaGetSymbolAddress((void**)&w1lo,      g_w1lo);
    cudaGetSymbolAddress((void**)&w2hi,      g_w2hi);
    cudaGetSymbolAddress((void**)&w2lo,      g_w2lo);
    cudaGetSymbolAddress((void**)&wohi,      g_wohi);
    cudaGetSymbolAddress((void**)&wolo,      g_wolo);
    cudaGetSymbolAddress((void**)&dis,       g_dis);
    cudaGetSymbolAddress((void**)&deg,       g_deg);
    cudaGetSymbolAddress((void**)&row_start, g_rowstart);
    cudaGetSymbolAddress((void**)&cursor,    g_cursor);
    cudaGetSymbolAddress((void**)&csr_src,   g_csr_src);

    // 80KB dynamic smem needs an explicit opt-in (attribute set, not an alloc)
    cudaFuncSetAttribute(mma_gemm<false>, cudaFuncAttributeMaxDynamicSharedMemorySize, GEMM_SMEM_BYTES);
    cudaFuncSetAttribute(mma_gemm<true>,  cudaFuncAttributeMaxDynamicSharedMemorySize, GEMM_SMEM_BYTES);

    dim3 gemm_grid(H / 128, (n + 127) / 128);
    int gather_grid = (n + 3) / 4;

    // kernel launches ordered so the 4th = mma_gemm (ncu capture window)
    detect_kernel<<<1, 32>>>(ei, n);
    cudaMemsetAsync(deg, 0, (size_t)n * sizeof(int));
    convert_x_kernel<<<(n * KP1 + 255) / 256, 256>>>(x, rni, ahi, alo, n);
    wsplit_kernel<<<(H * KP1 + 255) / 256, 256>>>(W1, w1hi, w1lo, KP1);

    // layer 1 GEMM (launch #4)
    mma_gemm<false><<<gemm_grid, 256, GEMM_SMEM_BYTES>>>(ahi, alo, w1hi, w1lo, nullptr, xt, n, KP1);

    // remaining prep + weight splits (all before first use)
    wsplit_kernel<<<(H * KP2 + 255) / 256, 256>>>(W2, w2hi, w2lo, KP2);
    wsplit_kernel<<<(H * KP2 + 255) / 256, 256>>>(Wout, wohi, wolo, KP2);
    count_deg_kernel<<<(e + 255) / 256, 256>>>(ei, deg, e, n);
    scan_dis_kernel<<<1, 1024>>>(deg, row_start, cursor, dis, n);
    csr_fill_kernel<<<(e + 255) / 256, 256>>>(ei, cursor, csr_src, e, n);

    // layer 1 aggregate -> relu -> split (feeds GEMM2)
    gather_kernel<<<gather_grid, 256>>>(xt, dis, row_start, deg, csr_src, b1, ahi, alo, n);

    // layer 2
    mma_gemm<false><<<gemm_grid, 256, GEMM_SMEM_BYTES>>>(ahi, alo, w2hi, w2lo, nullptr, xt, n, KP2);
    gather_kernel<<<gather_grid, 256>>>(xt, dis, row_start, deg, csr_src, b2, ahi, alo, n);

    // output
    mma_gemm<true><<<gemm_grid, 256, GEMM_SMEM_BYTES>>>(ahi, alo, wohi, wolo, bout, out, n, KP2);
}

// round 14
// speedup vs baseline: 1.0681x; 1.0104x over previous
#include <cuda_runtime.h>
#include <stdint.h>

#define NN_MAX 50000
#define E_MAX  800000
#define D_IN 128
#define D_RNI 32
#define D_H0 160
#define H 256
#define KP1 80      // k-pairs layer 1 (K=160)
#define KP2 128     // k-pairs layers 2/3 (K=256)

// ---------------- scratch (static device globals; no allocs allowed) --------
__device__ __align__(16) float    g_xt  [NN_MAX * H];
__device__ __align__(16) uint32_t g_ahi [NN_MAX * KP2];
__device__ __align__(16) uint32_t g_alo [NN_MAX * KP2];
__device__ __align__(16) uint32_t g_w1hi[H * KP1];
__device__ __align__(16) uint32_t g_w1lo[H * KP1];
__device__ __align__(16) uint32_t g_w2hi[H * KP2];
__device__ __align__(16) uint32_t g_w2lo[H * KP2];
__device__ __align__(16) uint32_t g_wohi[H * KP2];
__device__ __align__(16) uint32_t g_wolo[H * KP2];
__device__ __align__(16) float    g_dis[NN_MAX];
__device__ __align__(16) int      g_deg[NN_MAX];
__device__ __align__(16) int      g_rowstart[NN_MAX];
__device__ __align__(16) int      g_cursor[NN_MAX];
__device__ __align__(16) int      g_csr_src[E_MAX];
__device__ int g_is64;

// ---------------- bf16 split helpers -----------------------------------------
__device__ __forceinline__ uint32_t pack_bf(float lo, float hi) {
    uint32_t r;
    asm("cvt.rn.bf16x2.f32 %0, %1, %2;" : "=r"(r) : "f"(hi), "f"(lo));
    return r;
}
__device__ __forceinline__ void split_pair(float a0, float a1, uint32_t& h, uint32_t& l) {
    h = pack_bf(a0, a1);
    float h0 = __uint_as_float(h << 16);
    float h1 = __uint_as_float(h & 0xFFFF0000u);
    l = pack_bf(a0 - h0, a1 - h1);
}

// ---------------- edge-index dtype detection ---------------------------------
__global__ void detect_kernel(const void* __restrict__ ei, int n) {
    if (threadIdx.x == 0 && blockIdx.x == 0) {
        const long long* p = (const long long*)ei;
        int ok = 1;
        for (int i = 0; i < 512; i++) {
            long long v = p[i];
            if (v < 0 || v >= (long long)n) { ok = 0; break; }
        }
        g_is64 = ok;
    }
}

__device__ __forceinline__ int load_idx(const void* ei, long long i, int is64) {
    return is64 ? (int)((const long long*)ei)[i] : ((const int*)ei)[i];
}

__global__ void count_deg_kernel(const void* __restrict__ ei, int* __restrict__ deg,
                                 int e, int n) {
    int idx = blockIdx.x * blockDim.x + threadIdx.x;
    if (idx >= e) return;
    int is64 = g_is64;
    int d = load_idx(ei, (long long)e + idx, is64);
    if (d >= 0 && d < n) atomicAdd(&deg[d], 1);
}

__global__ void scan_dis_kernel(const int* __restrict__ deg, int* __restrict__ row_start,
                                int* __restrict__ cursor, float* __restrict__ dis, int n) {
    __shared__ int warpsum[32];
    int tid = threadIdx.x;
    int lane = tid & 31;
    int wid = tid >> 5;
    int carry = 0;
    for (int base = 0; base < n; base += 1024) {
        int i = base + tid;
        int v = (i < n) ? deg[i] : 0;
        int s = v;
#pragma unroll
        for (int off = 1; off < 32; off <<= 1) {
            int t = __shfl_up_sync(0xffffffff, s, off);
            if (lane >= off) s += t;
        }
        if (lane == 31) warpsum[wid] = s;
        __syncthreads();
        if (wid == 0) {
            int w = warpsum[lane];
#pragma unroll
            for (int off = 1; off < 32; off <<= 1) {
                int t = __shfl_up_sync(0xffffffff, w, off);
                if (lane >= off) w += t;
            }
            warpsum[lane] = w;
        }
        __syncthreads();
        int warp_excl = (wid == 0) ? 0 : warpsum[wid - 1];
        int total = warpsum[31];
        if (i < n) {
            int ex = carry + warp_excl + s - v;
            row_start[i] = ex;
            cursor[i] = ex;
            dis[i] = rsqrtf((float)v + 1.0f);
        }
        carry += total;
        __syncthreads();
    }
}

__global__ void csr_fill_kernel(const void* __restrict__ ei,
                                int* __restrict__ cursor, int* __restrict__ csr_src,
                                int e, int n) {
    int idx = blockIdx.x * blockDim.x + threadIdx.x;
    if (idx >= e) return;
    int is64 = g_is64;
    int d = load_idx(ei, (long long)e + idx, is64);
    int s = load_idx(ei, idx, is64);
    if (d < 0 || d >= n || s < 0 || s >= n) return;
    int p = atomicAdd(&cursor[d], 1);
    if (p >= 0 && p < E_MAX) csr_src[p] = s;
}

// convert [x|rni] -> pre-split bf16 hi/lo arrays, [node][KP1] uint32 each
__global__ void convert_x_kernel(const float* __restrict__ x, const float* __restrict__ rni,
                                 uint32_t* __restrict__ ahi, uint32_t* __restrict__ alo, int n) {
    int idx = blockIdx.x * blockDim.x + threadIdx.x;
    int total = n * KP1;
    if (idx >= total) return;
    int m = idx / KP1;
    int k = 2 * (idx - m * KP1);
    float v0, v1;
    if (k < D_IN) {
        v0 = x[(size_t)m * D_IN + k];
        v1 = x[(size_t)m * D_IN + k + 1];
    } else {
        v0 = rni[(size_t)m * D_RNI + (k - D_IN)];
        v1 = rni[(size_t)m * D_RNI + (k - D_IN) + 1];
    }
    uint32_t h, l;
    split_pair(v0, v1, h, l);
    ahi[idx] = h;
    alo[idx] = l;
}

// split + transpose weights: W[K][N] -> whi/wlo [N][KP]
__global__ void wsplit_kernel(const float* __restrict__ W,
                              uint32_t* __restrict__ whi, uint32_t* __restrict__ wlo, int kp_tot) {
    int idx = blockIdx.x * blockDim.x + threadIdx.x;
    if (idx >= H * kp_tot) return;
    int nn = idx / kp_tot;
    int kp = idx - nn * kp_tot;
    float v0 = W[(size_t)(2 * kp)     * H + nn];
    float v1 = W[(size_t)(2 * kp + 1) * H + nn];
    uint32_t h, l;
    split_pair(v0, v1, h, l);
    whi[idx] = h;
    wlo[idx] = l;
}

// gather-aggregate: 64 threads per node, 4 nodes per block.
__global__ void gather_kernel(const float* __restrict__ xt, const float* __restrict__ dis,
                              const int* __restrict__ row_start, const int* __restrict__ deg,
                              const int* __restrict__ csr_src, const float* __restrict__ bias,
                              uint32_t* __restrict__ ohi, uint32_t* __restrict__ olo, int n) {
    int node = blockIdx.x * 4 + (threadIdx.x >> 6);
    int c4 = threadIdx.x & 63;
    if (node >= n) return;
    int start = row_start[node];
    int d = deg[node];
    const float4* xt4 = reinterpret_cast<const float4*>(xt);

    float4 a0 = make_float4(0.f, 0.f, 0.f, 0.f);
    float4 a1 = make_float4(0.f, 0.f, 0.f, 0.f);
    int j = 0;
    for (; j + 2 <= d; j += 2) {
        int s0 = __ldg(&csr_src[start + j]);
        int s1 = __ldg(&csr_src[start + j + 1]);
        float w0 = __ldg(&dis[s0]);
        float w1 = __ldg(&dis[s1]);
        float4 v0 = __ldg(&xt4[(size_t)s0 * 64 + c4]);
        float4 v1 = __ldg(&xt4[(size_t)s1 * 64 + c4]);
        a0.x = fmaf(v0.x, w0, a0.x); a0.y = fmaf(v0.y, w0, a0.y);
        a0.z = fmaf(v0.z, w0, a0.z); a0.w = fmaf(v0.w, w0, a0.w);
        a1.x = fmaf(v1.x, w1, a1.x); a1.y = fmaf(v1.y, w1, a1.y);
        a1.z = fmaf(v1.z, w1, a1.z); a1.w = fmaf(v1.w, w1, a1.w);
    }
    if (j < d) {
        int s0 = __ldg(&csr_src[start + j]);
        float w0 = __ldg(&dis[s0]);
        float4 v0 = __ldg(&xt4[(size_t)s0 * 64 + c4]);
        a0.x = fmaf(v0.x, w0, a0.x); a0.y = fmaf(v0.y, w0, a0.y);
        a0.z = fmaf(v0.z, w0, a0.z); a0.w = fmaf(v0.w, w0, a0.w);
    }
    a0.x += a1.x; a0.y += a1.y; a0.z += a1.z; a0.w += a1.w;

    float dd = dis[node];
    float4 self = xt4[(size_t)node * 64 + c4];
    float4 b = reinterpret_cast<const float4*>(bias)[c4];
    float4 r;
    r.x = fmaxf(fmaf(dd, fmaf(self.x, dd, a0.x), b.x), 0.f);
    r.y = fmaxf(fmaf(dd, fmaf(self.y, dd, a0.y), b.y), 0.f);
    r.z = fmaxf(fmaf(dd, fmaf(self.z, dd, a0.z), b.z), 0.f);
    r.w = fmaxf(fmaf(dd, fmaf(self.w, dd, a0.w), b.w), 0.f);

    uint32_t h0, l0, h1, l1;
    split_pair(r.x, r.y, h0, l0);
    split_pair(r.z, r.w, h1, l1);
    size_t base = (size_t)node * KP2 + 2 * c4;
    *reinterpret_cast<uint2*>(ohi + base) = make_uint2(h0, h1);
    *reinterpret_cast<uint2*>(olo + base) = make_uint2(l0, l1);
}

// ---------------- bf16x3 tensor-core GEMM: 64x64 warp tile + cp.async ---------
// CTA 128x128, 128 threads = 4 warps (2m x 2n), warp tile 64x64 (Mi=4, Ni=8).
// Stage = 8 k-pairs (BK=16 elems). Smem rows = 8 words, XOR swizzle
// phys_word = word ^ (4*((row>>2)&1)) -> conflict-free fragment reads (R11-verified).
// cp.async 16B copies, 3-stage pipeline, no staging registers.

__device__ __forceinline__ void mma_bf16(float (&d)[4], const uint32_t (&a)[4],
                                         const uint32_t (&b)[2]) {
    asm("mma.sync.aligned.m16n8k16.row.col.f32.bf16.bf16.f32 "
        "{%0,%1,%2,%3}, {%4,%5,%6,%7}, {%8,%9}, {%0,%1,%2,%3};"
        : "+f"(d[0]), "+f"(d[1]), "+f"(d[2]), "+f"(d[3])
        : "r"(a[0]), "r"(a[1]), "r"(a[2]), "r"(a[3]), "r"(b[0]), "r"(b[1]));
}

__device__ __forceinline__ void cp_async16(uint32_t dst, const void* src, int sz) {
    asm volatile("cp.async.cg.shared.global [%0], [%1], 16, %2;"
                 :: "r"(dst), "l"(src), "r"(sz) : "memory");
}
#define CP_COMMIT() asm volatile("cp.async.commit_group;" ::: "memory")
#define CP_WAIT1()  asm volatile("cp.async.wait_group 1;" ::: "memory")

#define TSW 8                         // words per smem row
#define TILE_W (128 * TSW)            // 1024 words / 4KB per tile
#define STAGE_W (4 * TILE_W)          // A_hi, A_lo, B_hi, B_lo = 16KB
#define NSTAGE 3
#define GEMM_SMEM_BYTES (NSTAGE * STAGE_W * 4)  // 49152

template<bool ADD_BIAS>
__global__ void __launch_bounds__(128, 2)
mma_gemm(const uint32_t* __restrict__ Ahi, const uint32_t* __restrict__ Alo,
         const uint32_t* __restrict__ Whi, const uint32_t* __restrict__ Wlo,
         const float* __restrict__ bias, float* __restrict__ C,
         int M, int KPt) {
    extern __shared__ uint32_t sm[];
    const uint32_t sm_b = (uint32_t)__cvta_generic_to_shared(sm);
    const int NW = H;

    const int tid  = threadIdx.x;
    const int lane = tid & 31;
    const int warp = tid >> 5;        // 0..3
    const int wm = warp & 1;
    const int wn = warp >> 1;
    const int g = lane >> 2;
    const int t = lane & 3;
    const int bm = blockIdx.y * 128;
    const int bn = blockIdx.x * 128;

    const int cs = (g & 4) ? 4 : 0;
    const int fc0 = t ^ cs;
    const int fc1 = (t + 4) ^ cs;

    float acc[4][8][4];
#pragma unroll
    for (int mi = 0; mi < 4; mi++)
#pragma unroll
        for (int ni = 0; ni < 8; ni++)
#pragma unroll
            for (int r = 0; r < 4; r++) acc[mi][ni][r] = 0.0f;

    auto issue = [&](int s) {
        int kp0 = s * 8;
        uint32_t sb = sm_b + (s % NSTAGE) * (STAGE_W * 4);
        // A: 128 rows x 2 16B-chunks; 128 threads -> 2 iters
#pragma unroll
        for (int i = 0; i < 2; i++) {
            int idx = i * 128 + tid;
            int r = idx >> 1;
            int c = idx & 1;
            int gm = bm + r;
            int ok = (gm < M);
            int gmc = ok ? gm : 0;
            uint32_t dst = sb + (uint32_t)(r * 32 + ((c * 16) ^ ((r & 4) ? 16 : 0)));
            size_t off = (size_t)gmc * KPt + kp0 + 4 * c;
            int sz = ok ? 16 : 0;
            cp_async16(dst,                 Ahi + off, sz);
            cp_async16(dst + TILE_W * 4,    Alo + off, sz);
        }
        // B: 128 rows x 2 chunks (always valid, N=256)
#pragma unroll
        for (int i = 0; i < 2; i++) {
            int idx = i * 128 + tid;
            int r = idx >> 1;
            int c = idx & 1;
            uint32_t dst = sb + (uint32_t)(2 * TILE_W * 4 + r * 32 + ((c * 16) ^ ((r & 4) ? 16 : 0)));
            size_t off = (size_t)(bn + r) * KPt + kp0 + 4 * c;
            cp_async16(dst,                 Whi + off, 16);
            cp_async16(dst + TILE_W * 4,    Wlo + off, 16);
        }
    };

    auto compute = [&](int sb) {
        const uint32_t* A_hi = sm + sb * STAGE_W;
        const uint32_t* A_lo = A_hi + TILE_W;
        const uint32_t* B_hi = A_hi + 2 * TILE_W;
        const uint32_t* B_lo = A_hi + 3 * TILE_W;
        uint32_t ah[4][4], al[4][4];
#pragma unroll
        for (int mi = 0; mi < 4; mi++) {
            int r0 = (wm * 64 + mi * 16 + g) * TSW;
            int r1 = r0 + 8 * TSW;
            ah[mi][0] = A_hi[r0 + fc0]; ah[mi][1] = A_hi[r1 + fc0];
            ah[mi][2] = A_hi[r0 + fc1]; ah[mi][3] = A_hi[r1 + fc1];
            al[mi][0] = A_lo[r0 + fc0]; al[mi][1] = A_lo[r1 + fc0];
            al[mi][2] = A_lo[r0 + fc1]; al[mi][3] = A_lo[r1 + fc1];
        }
#pragma unroll
        for (int ni = 0; ni < 8; ni++) {
            int nr = (wn * 64 + ni * 8 + g) * TSW;
            uint32_t bh[2] = { B_hi[nr + fc0], B_hi[nr + fc1] };
            uint32_t bl[2] = { B_lo[nr + fc0], B_lo[nr + fc1] };
#pragma unroll
            for (int mi = 0; mi < 4; mi++) {
                mma_bf16(acc[mi][ni], ah[mi], bh);
                mma_bf16(acc[mi][ni], ah[mi], bl);
                mma_bf16(acc[mi][ni], al[mi], bh);
            }
        }
    };

    const int nst = KPt / 8;

    issue(0); CP_COMMIT();
    issue(1); CP_COMMIT();

    for (int s = 0; s < nst; s++) {
        CP_WAIT1();
        __syncthreads();
        compute(s % NSTAGE);
        __syncthreads();
        if (s + 2 < nst) issue(s + 2);
        CP_COMMIT();
    }

#pragma unroll
    for (int mi = 0; mi < 4; mi++) {
#pragma unroll
        for (int ni = 0; ni < 8; ni++) {
            int row = bm + wm * 64 + mi * 16 + g;
            int col = bn + wn * 64 + ni * 8 + t * 2;
            float bx = 0.f, by = 0.f;
            if (ADD_BIAS) {
                float2 bb = *reinterpret_cast<const float2*>(bias + col);
                bx = bb.x; by = bb.y;
            }
            if (row < M) {
                float2 v = make_float2(acc[mi][ni][0] + bx, acc[mi][ni][1] + by);
                *reinterpret_cast<float2*>(C + (size_t)row * NW + col) = v;
            }
            int row2 = row + 8;
            if (row2 < M) {
                float2 v = make_float2(acc[mi][ni][2] + bx, acc[mi][ni][3] + by);
                *reinterpret_cast<float2*>(C + (size_t)row2 * NW + col) = v;
            }
        }
    }
}

// ---------------- launch ------------------------------------------------------
extern "C" void kernel_launch(void* const* d_in, const int* in_sizes, int n_in,
                              void* d_out, int out_size) {
    const float* x     = (const float*)d_in[0];
    const float* rni   = (const float*)d_in[1];
    const void*  ei    = d_in[2];
    const float* W1    = (const float*)d_in[3];
    const float* b1    = (const float*)d_in[4];
    const float* W2    = (const float*)d_in[5];
    const float* b2    = (const float*)d_in[6];
    const float* Wout  = (const float*)d_in[7];
    const float* bout  = (const float*)d_in[8];
    float* out = (float*)d_out;

    int n = in_sizes[0] / D_IN;
    int e = in_sizes[2] / 2;

    float *xt, *dis;
    uint32_t *ahi, *alo, *w1hi, *w1lo, *w2hi, *w2lo, *wohi, *wolo;
    int *deg, *row_start, *cursor, *csr_src;
    cudaGetSymbolAddress((void**)&xt,        g_xt);
    cudaGetSymbolAddress((void**)&ahi,       g_ahi);
    cudaGetSymbolAddress((void**)&alo,       g_alo);
    cudaGetSymbolAddress((void**)&w1hi,      g_w1hi);
    cudaGetSymbolAddress((void**)&w1lo,      g_w1lo);
    cudaGetSymbolAddress((void**)&w2hi,      g_w2hi);
    cudaGetSymbolAddress((void**)&w2lo,      g_w2lo);
    cudaGetSymbolAddress((void**)&wohi,      g_wohi);
    cudaGetSymbolAddress((void**)&wolo,      g_wolo);
    cudaGetSymbolAddress((void**)&dis,       g_dis);
    cudaGetSymbolAddress((void**)&deg,       g_deg);
    cudaGetSymbolAddress((void**)&row_start, g_rowstart);
    cudaGetSymbolAddress((void**)&cursor,    g_cursor);
    cudaGetSymbolAddress((void**)&csr_src,   g_csr_src);

    cudaFuncSetAttribute(mma_gemm<false>, cudaFuncAttributeMaxDynamicSharedMemorySize, GEMM_SMEM_BYTES);
    cudaFuncSetAttribute(mma_gemm<true>,  cudaFuncAttributeMaxDynamicSharedMemorySize, GEMM_SMEM_BYTES);

    dim3 gemm_grid(H / 128, (n + 127) / 128);
    int gather_grid = (n + 3) / 4;

    // kernel launches ordered so the 4th = mma_gemm (ncu capture window)
    detect_kernel<<<1, 32>>>(ei, n);
    cudaMemsetAsync(deg, 0, (size_t)n * sizeof(int));
    convert_x_kernel<<<(n * KP1 + 255) / 256, 256>>>(x, rni, ahi, alo, n);
    wsplit_kernel<<<(H * KP1 + 255) / 256, 256>>>(W1, w1hi, w1lo, KP1);

    // layer 1 GEMM (launch #4)
    mma_gemm<false><<<gemm_grid, 128, GEMM_SMEM_BYTES>>>(ahi, alo, w1hi, w1lo, nullptr, xt, n, KP1);

    // remaining prep + weight splits (all before first use)
    wsplit_kernel<<<(H * KP2 + 255) / 256, 256>>>(W2, w2hi, w2lo, KP2);
    wsplit_kernel<<<(H * KP2 + 255) / 256, 256>>>(Wout, wohi, wolo, KP2);
    count_deg_kernel<<<(e + 255) / 256, 256>>>(ei, deg, e, n);
    scan_dis_kernel<<<1, 1024>>>(deg, row_start, cursor, dis, n);
    csr_fill_kernel<<<(e + 255) / 256, 256>>>(ei, cursor, csr_src, e, n);

    // layer 1 aggregate -> relu -> split (feeds GEMM2)
    gather_kernel<<<gather_grid, 256>>>(xt, dis, row_start, deg, csr_src, b1, ahi, alo, n);

    // layer 2
    mma_gemm<false><<<gemm_grid, 128, GEMM_SMEM_BYTES>>>(ahi, alo, w2hi, w2lo, nullptr, xt, n, KP2);
    gather_kernel<<<gather_grid, 256>>>(xt, dis, row_start, deg, csr_src, b2, ahi, alo, n);

    // output
    mma_gemm<true><<<gemm_grid, 128, GEMM_SMEM_BYTES>>>(ahi, alo, wohi, wolo, bout, out, n, KP2);
}

// round 15
// speedup vs baseline: 1.1128x; 1.0419x over previous
#include <cuda_runtime.h>
#include <stdint.h>

#define NN_MAX 50000
#define E_MAX  800000
#define D_IN 128
#define D_RNI 32
#define D_H0 160
#define H 256
#define KP1 80      // k-pairs layer 1 (K=160)
#define KP2 128     // k-pairs layers 2/3 (K=256)

// ---------------- scratch (static device globals; no allocs allowed) --------
__device__ __align__(16) float    g_xt  [NN_MAX * H];
__device__ __align__(16) uint32_t g_ahi [NN_MAX * KP2];
__device__ __align__(16) uint32_t g_alo [NN_MAX * KP2];
__device__ __align__(16) uint32_t g_w1hi[H * KP1];
__device__ __align__(16) uint32_t g_w1lo[H * KP1];
__device__ __align__(16) uint32_t g_w2hi[H * KP2];
__device__ __align__(16) uint32_t g_w2lo[H * KP2];
__device__ __align__(16) uint32_t g_wohi[H * KP2];
__device__ __align__(16) uint32_t g_wolo[H * KP2];
__device__ __align__(16) float    g_dis[NN_MAX];
__device__ __align__(16) int      g_deg[NN_MAX];
__device__ __align__(16) int      g_rowstart[NN_MAX];
__device__ __align__(16) int      g_cursor[NN_MAX];
__device__ __align__(16) int      g_csr_src[E_MAX];
__device__ int g_is64;

// ---------------- bf16 split helpers -----------------------------------------
__device__ __forceinline__ uint32_t pack_bf(float lo, float hi) {
    uint32_t r;
    asm("cvt.rn.bf16x2.f32 %0, %1, %2;" : "=r"(r) : "f"(hi), "f"(lo));
    return r;
}
__device__ __forceinline__ void split_pair(float a0, float a1, uint32_t& h, uint32_t& l) {
    h = pack_bf(a0, a1);
    float h0 = __uint_as_float(h << 16);
    float h1 = __uint_as_float(h & 0xFFFF0000u);
    l = pack_bf(a0 - h0, a1 - h1);
}

// ---------------- edge-index dtype detection ---------------------------------
__global__ void detect_kernel(const void* __restrict__ ei, int n) {
    if (threadIdx.x == 0 && blockIdx.x == 0) {
        const long long* p = (const long long*)ei;
        int ok = 1;
        for (int i = 0; i < 512; i++) {
            long long v = p[i];
            if (v < 0 || v >= (long long)n) { ok = 0; break; }
        }
        g_is64 = ok;
    }
}

__device__ __forceinline__ int load_idx(const void* ei, long long i, int is64) {
    return is64 ? (int)((const long long*)ei)[i] : ((const int*)ei)[i];
}

__global__ void count_deg_kernel(const void* __restrict__ ei, int* __restrict__ deg,
                                 int e, int n) {
    int idx = blockIdx.x * blockDim.x + threadIdx.x;
    if (idx >= e) return;
    int is64 = g_is64;
    int d = load_idx(ei, (long long)e + idx, is64);
    if (d >= 0 && d < n) atomicAdd(&deg[d], 1);
}

__global__ void scan_dis_kernel(const int* __restrict__ deg, int* __restrict__ row_start,
                                int* __restrict__ cursor, float* __restrict__ dis, int n) {
    __shared__ int warpsum[32];
    int tid = threadIdx.x;
    int lane = tid & 31;
    int wid = tid >> 5;
    int carry = 0;
    for (int base = 0; base < n; base += 1024) {
        int i = base + tid;
        int v = (i < n) ? deg[i] : 0;
        int s = v;
#pragma unroll
        for (int off = 1; off < 32; off <<= 1) {
            int t = __shfl_up_sync(0xffffffff, s, off);
            if (lane >= off) s += t;
        }
        if (lane == 31) warpsum[wid] = s;
        __syncthreads();
        if (wid == 0) {
            int w = warpsum[lane];
#pragma unroll
            for (int off = 1; off < 32; off <<= 1) {
                int t = __shfl_up_sync(0xffffffff, w, off);
                if (lane >= off) w += t;
            }
            warpsum[lane] = w;
        }
        __syncthreads();
        int warp_excl = (wid == 0) ? 0 : warpsum[wid - 1];
        int total = warpsum[31];
        if (i < n) {
            int ex = carry + warp_excl + s - v;
            row_start[i] = ex;
            cursor[i] = ex;
            dis[i] = rsqrtf((float)v + 1.0f);
        }
        carry += total;
        __syncthreads();
    }
}

__global__ void csr_fill_kernel(const void* __restrict__ ei,
                                int* __restrict__ cursor, int* __restrict__ csr_src,
                                int e, int n) {
    int idx = blockIdx.x * blockDim.x + threadIdx.x;
    if (idx >= e) return;
    int is64 = g_is64;
    int d = load_idx(ei, (long long)e + idx, is64);
    int s = load_idx(ei, idx, is64);
    if (d < 0 || d >= n || s < 0 || s >= n) return;
    int p = atomicAdd(&cursor[d], 1);
    if (p >= 0 && p < E_MAX) csr_src[p] = s;
}

// convert [x|rni] -> pre-split bf16 hi/lo arrays, [node][KP1] uint32 each
__global__ void convert_x_kernel(const float* __restrict__ x, const float* __restrict__ rni,
                                 uint32_t* __restrict__ ahi, uint32_t* __restrict__ alo, int n) {
    int idx = blockIdx.x * blockDim.x + threadIdx.x;
    int total = n * KP1;
    if (idx >= total) return;
    int m = idx / KP1;
    int k = 2 * (idx - m * KP1);
    float v0, v1;
    if (k < D_IN) {
        v0 = x[(size_t)m * D_IN + k];
        v1 = x[(size_t)m * D_IN + k + 1];
    } else {
        v0 = rni[(size_t)m * D_RNI + (k - D_IN)];
        v1 = rni[(size_t)m * D_RNI + (k - D_IN) + 1];
    }
    uint32_t h, l;
    split_pair(v0, v1, h, l);
    ahi[idx] = h;
    alo[idx] = l;
}

// split + transpose weights: W[K][N] -> whi/wlo [N][KP]
__global__ void wsplit_kernel(const float* __restrict__ W,
                              uint32_t* __restrict__ whi, uint32_t* __restrict__ wlo, int kp_tot) {
    int idx = blockIdx.x * blockDim.x + threadIdx.x;
    if (idx >= H * kp_tot) return;
    int nn = idx / kp_tot;
    int kp = idx - nn * kp_tot;
    float v0 = W[(size_t)(2 * kp)     * H + nn];
    float v1 = W[(size_t)(2 * kp + 1) * H + nn];
    uint32_t h, l;
    split_pair(v0, v1, h, l);
    whi[idx] = h;
    wlo[idx] = l;
}

// gather-aggregate: 64 threads per node, 4 nodes per block.
__global__ void gather_kernel(const float* __restrict__ xt, const float* __restrict__ dis,
                              const int* __restrict__ row_start, const int* __restrict__ deg,
                              const int* __restrict__ csr_src, const float* __restrict__ bias,
                              uint32_t* __restrict__ ohi, uint32_t* __restrict__ olo, int n) {
    int node = blockIdx.x * 4 + (threadIdx.x >> 6);
    int c4 = threadIdx.x & 63;
    if (node >= n) return;
    int start = row_start[node];
    int d = deg[node];
    const float4* xt4 = reinterpret_cast<const float4*>(xt);

    float4 a0 = make_float4(0.f, 0.f, 0.f, 0.f);
    float4 a1 = make_float4(0.f, 0.f, 0.f, 0.f);
    int j = 0;
    for (; j + 2 <= d; j += 2) {
        int s0 = __ldg(&csr_src[start + j]);
        int s1 = __ldg(&csr_src[start + j + 1]);
        float w0 = __ldg(&dis[s0]);
        float w1 = __ldg(&dis[s1]);
        float4 v0 = __ldg(&xt4[(size_t)s0 * 64 + c4]);
        float4 v1 = __ldg(&xt4[(size_t)s1 * 64 + c4]);
        a0.x = fmaf(v0.x, w0, a0.x); a0.y = fmaf(v0.y, w0, a0.y);
        a0.z = fmaf(v0.z, w0, a0.z); a0.w = fmaf(v0.w, w0, a0.w);
        a1.x = fmaf(v1.x, w1, a1.x); a1.y = fmaf(v1.y, w1, a1.y);
        a1.z = fmaf(v1.z, w1, a1.z); a1.w = fmaf(v1.w, w1, a1.w);
    }
    if (j < d) {
        int s0 = __ldg(&csr_src[start + j]);
        float w0 = __ldg(&dis[s0]);
        float4 v0 = __ldg(&xt4[(size_t)s0 * 64 + c4]);
        a0.x = fmaf(v0.x, w0, a0.x); a0.y = fmaf(v0.y, w0, a0.y);
        a0.z = fmaf(v0.z, w0, a0.z); a0.w = fmaf(v0.w, w0, a0.w);
    }
    a0.x += a1.x; a0.y += a1.y; a0.z += a1.z; a0.w += a1.w;

    float dd = dis[node];
    float4 self = xt4[(size_t)node * 64 + c4];
    float4 b = reinterpret_cast<const float4*>(bias)[c4];
    float4 r;
    r.x = fmaxf(fmaf(dd, fmaf(self.x, dd, a0.x), b.x), 0.f);
    r.y = fmaxf(fmaf(dd, fmaf(self.y, dd, a0.y), b.y), 0.f);
    r.z = fmaxf(fmaf(dd, fmaf(self.z, dd, a0.z), b.z), 0.f);
    r.w = fmaxf(fmaf(dd, fmaf(self.w, dd, a0.w), b.w), 0.f);

    uint32_t h0, l0, h1, l1;
    split_pair(r.x, r.y, h0, l0);
    split_pair(r.z, r.w, h1, l1);
    size_t base = (size_t)node * KP2 + 2 * c4;
    *reinterpret_cast<uint2*>(ohi + base) = make_uint2(h0, h1);
    *reinterpret_cast<uint2*>(olo + base) = make_uint2(l0, l1);
}

// ---------------- bf16x3 tensor-core GEMM: 64x64 warp tile + cp.async ---------
// CTA 128x128, 128 threads = 4 warps (2m x 2n), warp tile 64x64 (Mi=4, Ni=8).
// Stage = 8 k-pairs (BK=16 elems). Smem rows = 8 words, XOR swizzle
// phys_word = word ^ (4*((row>>2)&1)) -> conflict-free fragment reads.
// cp.async 16B copies, 3-stage pipeline. MMA issue is product-major per ni so
// same-accumulator reuse distance is 4 (hides HMMA latency).

__device__ __forceinline__ void mma_bf16(float (&d)[4], const uint32_t (&a)[4],
                                         const uint32_t (&b)[2]) {
    asm("mma.sync.aligned.m16n8k16.row.col.f32.bf16.bf16.f32 "
        "{%0,%1,%2,%3}, {%4,%5,%6,%7}, {%8,%9}, {%0,%1,%2,%3};"
        : "+f"(d[0]), "+f"(d[1]), "+f"(d[2]), "+f"(d[3])
        : "r"(a[0]), "r"(a[1]), "r"(a[2]), "r"(a[3]), "r"(b[0]), "r"(b[1]));
}

__device__ __forceinline__ void cp_async16(uint32_t dst, const void* src, int sz) {
    asm volatile("cp.async.cg.shared.global [%0], [%1], 16, %2;"
                 :: "r"(dst), "l"(src), "r"(sz) : "memory");
}
#define CP_COMMIT() asm volatile("cp.async.commit_group;" ::: "memory")
#define CP_WAIT1()  asm volatile("cp.async.wait_group 1;" ::: "memory")

#define TSW 8                         // words per smem row
#define TILE_W (128 * TSW)            // 1024 words / 4KB per tile
#define STAGE_W (4 * TILE_W)          // A_hi, A_lo, B_hi, B_lo = 16KB
#define NSTAGE 3
#define GEMM_SMEM_BYTES (NSTAGE * STAGE_W * 4)  // 49152

template<bool ADD_BIAS>
__global__ void __launch_bounds__(128, 2)
mma_gemm(const uint32_t* __restrict__ Ahi, const uint32_t* __restrict__ Alo,
         const uint32_t* __restrict__ Whi, const uint32_t* __restrict__ Wlo,
         const float* __restrict__ bias, float* __restrict__ C,
         int M, int KPt) {
    extern __shared__ uint32_t sm[];
    const uint32_t sm_b = (uint32_t)__cvta_generic_to_shared(sm);
    const int NW = H;

    const int tid  = threadIdx.x;
    const int lane = tid & 31;
    const int warp = tid >> 5;        // 0..3
    const int wm = warp & 1;
    const int wn = warp >> 1;
    const int g = lane >> 2;
    const int t = lane & 3;
    const int bm = blockIdx.y * 128;
    const int bn = blockIdx.x * 128;

    const int cs = (g & 4) ? 4 : 0;
    const int fc0 = t ^ cs;
    const int fc1 = (t + 4) ^ cs;

    float acc[4][8][4];
#pragma unroll
    for (int mi = 0; mi < 4; mi++)
#pragma unroll
        for (int ni = 0; ni < 8; ni++)
#pragma unroll
            for (int r = 0; r < 4; r++) acc[mi][ni][r] = 0.0f;

    auto issue = [&](int s) {
        int kp0 = s * 8;
        uint32_t sb = sm_b + (s % NSTAGE) * (STAGE_W * 4);
#pragma unroll
        for (int i = 0; i < 2; i++) {
            int idx = i * 128 + tid;
            int r = idx >> 1;
            int c = idx & 1;
            int gm = bm + r;
            int ok = (gm < M);
            int gmc = ok ? gm : 0;
            uint32_t dst = sb + (uint32_t)(r * 32 + ((c * 16) ^ ((r & 4) ? 16 : 0)));
            size_t off = (size_t)gmc * KPt + kp0 + 4 * c;
            int sz = ok ? 16 : 0;
            cp_async16(dst,                 Ahi + off, sz);
            cp_async16(dst + TILE_W * 4,    Alo + off, sz);
        }
#pragma unroll
        for (int i = 0; i < 2; i++) {
            int idx = i * 128 + tid;
            int r = idx >> 1;
            int c = idx & 1;
            uint32_t dst = sb + (uint32_t)(2 * TILE_W * 4 + r * 32 + ((c * 16) ^ ((r & 4) ? 16 : 0)));
            size_t off = (size_t)(bn + r) * KPt + kp0 + 4 * c;
            cp_async16(dst,                 Whi + off, 16);
            cp_async16(dst + TILE_W * 4,    Wlo + off, 16);
        }
    };

    auto compute = [&](int sb) {
        const uint32_t* A_hi = sm + sb * STAGE_W;
        const uint32_t* A_lo = A_hi + TILE_W;
        const uint32_t* B_hi = A_hi + 2 * TILE_W;
        const uint32_t* B_lo = A_hi + 3 * TILE_W;
        uint32_t ah[4][4], al[4][4];
#pragma unroll
        for (int mi = 0; mi < 4; mi++) {
            int r0 = (wm * 64 + mi * 16 + g) * TSW;
            int r1 = r0 + 8 * TSW;
            ah[mi][0] = A_hi[r0 + fc0]; ah[mi][1] = A_hi[r1 + fc0];
            ah[mi][2] = A_hi[r0 + fc1]; ah[mi][3] = A_hi[r1 + fc1];
            al[mi][0] = A_lo[r0 + fc0]; al[mi][1] = A_lo[r1 + fc0];
            al[mi][2] = A_lo[r0 + fc1]; al[mi][3] = A_lo[r1 + fc1];
        }
#pragma unroll
        for (int ni = 0; ni < 8; ni++) {
            int nr = (wn * 64 + ni * 8 + g) * TSW;
            uint32_t bh[2] = { B_hi[nr + fc0], B_hi[nr + fc1] };
            uint32_t bl[2] = { B_lo[nr + fc0], B_lo[nr + fc1] };
            // product-major: same-acc reuse distance = 4 MMAs (hides HMMA latency)
#pragma unroll
            for (int mi = 0; mi < 4; mi++) mma_bf16(acc[mi][ni], ah[mi], bh);
#pragma unroll
            for (int mi = 0; mi < 4; mi++) mma_bf16(acc[mi][ni], ah[mi], bl);
#pragma unroll
            for (int mi = 0; mi < 4; mi++) mma_bf16(acc[mi][ni], al[mi], bh);
        }
    };

    const int nst = KPt / 8;

    issue(0); CP_COMMIT();
    issue(1); CP_COMMIT();

    for (int s = 0; s < nst; s++) {
        CP_WAIT1();
        __syncthreads();
        compute(s % NSTAGE);
        // no barrier needed here: issue targets stage (s+2)%3 == (s-1)%3,
        // which every warp finished computing before this iteration's barrier
        if (s + 2 < nst) issue(s + 2);
        CP_COMMIT();
    }

#pragma unroll
    for (int mi = 0; mi < 4; mi++) {
#pragma unroll
        for (int ni = 0; ni < 8; ni++) {
            int row = bm + wm * 64 + mi * 16 + g;
            int col = bn + wn * 64 + ni * 8 + t * 2;
            float bx = 0.f, by = 0.f;
            if (ADD_BIAS) {
                float2 bb = *reinterpret_cast<const float2*>(bias + col);
                bx = bb.x; by = bb.y;
            }
            if (row < M) {
                float2 v = make_float2(acc[mi][ni][0] + bx, acc[mi][ni][1] + by);
                *reinterpret_cast<float2*>(C + (size_t)row * NW + col) = v;
            }
            int row2 = row + 8;
            if (row2 < M) {
                float2 v = make_float2(acc[mi][ni][2] + bx, acc[mi][ni][3] + by);
                *reinterpret_cast<float2*>(C + (size_t)row2 * NW + col) = v;
            }
        }
    }
}

// ---------------- launch ------------------------------------------------------
extern "C" void kernel_launch(void* const* d_in, const int* in_sizes, int n_in,
                              void* d_out, int out_size) {
    const float* x     = (const float*)d_in[0];
    const float* rni   = (const float*)d_in[1];
    const void*  ei    = d_in[2];
    const float* W1    = (const float*)d_in[3];
    const float* b1    = (const float*)d_in[4];
    const float* W2    = (const float*)d_in[5];
    const float* b2    = (const float*)d_in[6];
    const float* Wout  = (const float*)d_in[7];
    const float* bout  = (const float*)d_in[8];
    float* out = (float*)d_out;

    int n = in_sizes[0] / D_IN;
    int e = in_sizes[2] / 2;

    float *xt, *dis;
    uint32_t *ahi, *alo, *w1hi, *w1lo, *w2hi, *w2lo, *wohi, *wolo;
    int *deg, *row_start, *cursor, *csr_src;
    cudaGetSymbolAddress((void**)&xt,        g_xt);
    cudaGetSymbolAddress((void**)&ahi,       g_ahi);
    cudaGetSymbolAddress((void**)&alo,       g_alo);
    cudaGetSymbolAddress((void**)&w1hi,      g_w1hi);
    cudaGetSymbolAddress((void**)&w1lo,      g_w1lo);
    cudaGetSymbolAddress((void**)&w2hi,      g_w2hi);
    cudaGetSymbolAddress((void**)&w2lo,      g_w2lo);
    cudaGetSymbolAddress((void**)&wohi,      g_wohi);
    cudaGetSymbolAddress((void**)&wolo,      g_wolo);
    cudaGetSymbolAddress((void**)&dis,       g_dis);
    cudaGetSymbolAddress((void**)&deg,       g_deg);
    cudaGetSymbolAddress((void**)&row_start, g_rowstart);
    cudaGetSymbolAddress((void**)&cursor,    g_cursor);
    cudaGetSymbolAddress((void**)&csr_src,   g_csr_src);

    cudaFuncSetAttribute(mma_gemm<false>, cudaFuncAttributeMaxDynamicSharedMemorySize, GEMM_SMEM_BYTES);
    cudaFuncSetAttribute(mma_gemm<true>,  cudaFuncAttributeMaxDynamicSharedMemorySize, GEMM_SMEM_BYTES);

    dim3 gemm_grid(H / 128, (n + 127) / 128);
    int gather_grid = (n + 3) / 4;

    // kernel launches ordered so the 4th = mma_gemm (ncu capture window)
    detect_kernel<<<1, 32>>>(ei, n);
    cudaMemsetAsync(deg, 0, (size_t)n * sizeof(int));
    convert_x_kernel<<<(n * KP1 + 255) / 256, 256>>>(x, rni, ahi, alo, n);
    wsplit_kernel<<<(H * KP1 + 255) / 256, 256>>>(W1, w1hi, w1lo, KP1);

    // layer 1 GEMM (launch #4)
    mma_gemm<false><<<gemm_grid, 128, GEMM_SMEM_BYTES>>>(ahi, alo, w1hi, w1lo, nullptr, xt, n, KP1);

    // remaining prep + weight splits (all before first use)
    wsplit_kernel<<<(H * KP2 + 255) / 256, 256>>>(W2, w2hi, w2lo, KP2);
    wsplit_kernel<<<(H * KP2 + 255) / 256, 256>>>(Wout, wohi, wolo, KP2);
    count_deg_kernel<<<(e + 255) / 256, 256>>>(ei, deg, e, n);
    scan_dis_kernel<<<1, 1024>>>(deg, row_start, cursor, dis, n);
    csr_fill_kernel<<<(e + 255) / 256, 256>>>(ei, cursor, csr_src, e, n);

    // layer 1 aggregate -> relu -> split (feeds GEMM2)
    gather_kernel<<<gather_grid, 256>>>(xt, dis, row_start, deg, csr_src, b1, ahi, alo, n);

    // layer 2
    mma_gemm<false><<<gemm_grid, 128, GEMM_SMEM_BYTES>>>(ahi, alo, w2hi, w2lo, nullptr, xt, n, KP2);
    gather_kernel<<<gather_grid, 256>>>(xt, dis, row_start, deg, csr_src, b2, ahi, alo, n);

    // output
    mma_gemm<true><<<gemm_grid, 128, GEMM_SMEM_BYTES>>>(ahi, alo, wohi, wolo, bout, out, n, KP2);
}